// round 1
// baseline (speedup 1.0000x reference)
#include <cuda_runtime.h>
#include <math.h>

#define H 256
#define W 256
#define B 4
#define HW 65536
#define P4 16384   // HW / 4

// ---------------- scratch (static device globals; no runtime allocation) ----
__device__ float g_fin [B * 24  * HW];   //  24 MB
__device__ float g_buf0[B * 64  * HW];   //  64 MB
__device__ float g_buf1[B * 64  * HW];   //  64 MB
__device__ float g_din [B * 100 * HW];   // 100 MB

// ---------------- elementwise: build fusion_in (24ch) -----------------------
__global__ void prep_kernel(const float* __restrict__ ft0,
                            const float* __restrict__ ft1,
                            const float* __restrict__ gup,
                            const float* __restrict__ ca,
                            const float* __restrict__ cb,
                            float* __restrict__ fin)
{
    int i = blockIdx.x * blockDim.x + threadIdx.x;   // 0 .. B*P4
    if (i >= B * P4) return;
    int b = i >> 14;
    int p = i & (P4 - 1);
    const float4* f0 = (const float4*)(ft0 + (size_t)b * 64 * HW);
    const float4* f1 = (const float4*)(ft1 + (size_t)b * 64 * HW);
    const float4* gu = (const float4*)(gup + (size_t)b * 4 * HW);
    float4*       fo = (float4*)(fin + (size_t)b * 24 * HW);
    float a = *ca, bb = *cb;

#pragma unroll
    for (int c = 0; c < 16; c++) {
        float4 t0 = f0[(size_t)c * P4 + p];
        float4 t1 = f1[(size_t)c * P4 + p];
        float4 r;
        r.x = fabsf(t1.x - t0.x); r.y = fabsf(t1.y - t0.y);
        r.z = fabsf(t1.z - t0.z); r.w = fabsf(t1.w - t0.w);
        fo[(size_t)c * P4 + p] = r;
    }
#pragma unroll
    for (int c = 0; c < 4; c++)
        fo[(size_t)(16 + c) * P4 + p] = gu[(size_t)c * P4 + p];
#pragma unroll
    for (int c = 0; c < 4; c++) {
        float4 t1 = f1[(size_t)c * P4 + p];
        float4 r;
        r.x = fminf(fmaxf(t1.x, 0.f), 1.f) * a + bb;
        r.y = fminf(fmaxf(t1.y, 0.f), 1.f) * a + bb;
        r.z = fminf(fmaxf(t1.z, 0.f), 1.f) * a + bb;
        r.w = fminf(fmaxf(t1.w, 0.f), 1.f) * a + bb;
        fo[(size_t)(20 + c) * P4 + p] = r;
    }
}

// ---------------- elementwise: fusion_out / sigma / denoise_in --------------
__global__ void fuse_kernel(const float* __restrict__ ft0,
                            const float* __restrict__ ft1,
                            const float* __restrict__ dd,
                            const float* __restrict__ ca,
                            const float* __restrict__ cb,
                            const float* __restrict__ gamma,   // in d_out
                            float* __restrict__ out_fusion,    // in d_out
                            float* __restrict__ out_sigma,     // in d_out
                            float* __restrict__ din)
{
    int i = blockIdx.x * blockDim.x + threadIdx.x;
    if (i >= B * P4) return;
    int b = i >> 14;
    int p = i & (P4 - 1);
    const float4* f0 = (const float4*)(ft0 + (size_t)b * 64 * HW);
    const float4* f1 = (const float4*)(ft1 + (size_t)b * 64 * HW);
    const float4* dv = (const float4*)(dd  + (size_t)b * 16 * HW);
    const float4* gv = (const float4*)(gamma + (size_t)b * 4 * HW);
    float4* ofu = (float4*)(out_fusion + (size_t)b * 64 * HW);
    float4* osg = (float4*)(out_sigma  + (size_t)b * 4  * HW);
    float4* di  = (float4*)(din + (size_t)b * 100 * HW);
    float a = *ca, bb = *cb;

    float4 g[4];
#pragma unroll
    for (int c = 0; c < 4; c++) g[c] = gv[(size_t)c * P4 + p];

#pragma unroll
    for (int c = 0; c < 64; c++) {
        float4 t0 = f0[(size_t)c * P4 + p];
        float4 t1 = f1[(size_t)c * P4 + p];
        float4 gm = g[c >> 4];
        float4 r;
        r.x = t0.x + gm.x * (t1.x - t0.x);
        r.y = t0.y + gm.y * (t1.y - t0.y);
        r.z = t0.z + gm.z * (t1.z - t0.z);
        r.w = t0.w + gm.w * (t1.w - t0.w);
        ofu[(size_t)c * P4 + p] = r;
        di [(size_t)c * P4 + p] = r;
        if (c < 16) di[(size_t)(64 + c) * P4 + p] = t1;   // ll1
    }
#pragma unroll
    for (int c = 0; c < 16; c++)
        di[(size_t)(80 + c) * P4 + p] = dv[(size_t)c * P4 + p];
#pragma unroll
    for (int c = 0; c < 4; c++) {
        float4 t0 = f0[(size_t)c * P4 + p];
        float4 t1 = f1[(size_t)c * P4 + p];
        float4 gm = g[c];
        float4 s;
        float s0, s1, om;
        s0 = fminf(fmaxf(t0.x,0.f),1.f)*a+bb; s1 = fminf(fmaxf(t1.x,0.f),1.f)*a+bb;
        om = 1.f - gm.x; s.x = om*om*s0 + gm.x*gm.x*s1;
        s0 = fminf(fmaxf(t0.y,0.f),1.f)*a+bb; s1 = fminf(fmaxf(t1.y,0.f),1.f)*a+bb;
        om = 1.f - gm.y; s.y = om*om*s0 + gm.y*gm.y*s1;
        s0 = fminf(fmaxf(t0.z,0.f),1.f)*a+bb; s1 = fminf(fmaxf(t1.z,0.f),1.f)*a+bb;
        om = 1.f - gm.z; s.z = om*om*s0 + gm.z*gm.z*s1;
        s0 = fminf(fmaxf(t0.w,0.f),1.f)*a+bb; s1 = fminf(fmaxf(t1.w,0.f),1.f)*a+bb;
        om = 1.f - gm.w; s.w = om*om*s0 + gm.w*gm.w*s1;
        osg[(size_t)c * P4 + p] = s;
        di [(size_t)(96 + c) * P4 + p] = s;
    }
}

// ---------------- direct 3x3 conv, pad 1 ------------------------------------
// Block: 256 threads = 32x8 output tile. COUT_PB output channels per thread.
// CIN processed 4 channels per smem step. Weights staged [ci][k][co] for
// float4 broadcast LDS. ACT: 0=relu, 1=sigmoid, 2=none.
template <int CIN, int COUT, int COUT_PB, int ACT>
__global__ void conv3x3_kernel(const float* __restrict__ in,
                               const float* __restrict__ wgt,
                               const float* __restrict__ bias,
                               float* __restrict__ out)
{
    const int tid = threadIdx.x;
    const int tx = tid & 31;
    const int ty = tid >> 5;
    const int bx = blockIdx.x * 32;
    const int by = blockIdx.y * 8;
    const int groups = COUT / COUT_PB;
    const int b   = blockIdx.z / groups;
    const int co0 = (blockIdx.z % groups) * COUT_PB;

    __shared__ float sw[4 * 9 * COUT_PB];
    __shared__ float sin_t[4][10][34];

    const float* inb = in + (size_t)b * CIN * HW;

    float acc[COUT_PB];
#pragma unroll
    for (int i = 0; i < COUT_PB; i++) acc[i] = bias[co0 + i];

    for (int c0 = 0; c0 < CIN; c0 += 4) {
        __syncthreads();
        // stage weights for this 4-cin slab: layout [ci][k][co]
        for (int i = tid; i < 4 * 9 * COUT_PB; i += 256) {
            int co   = i % COUT_PB;
            int rest = i / COUT_PB;      // ci*9 + k
            int ci   = rest / 9;
            int k    = rest % 9;
            sw[i] = wgt[((size_t)(co0 + co) * CIN + (c0 + ci)) * 9 + k];
        }
        // stage input tile 4 x 10 x 34 (halo 1)
        for (int i = tid; i < 4 * 340; i += 256) {
            int ci = i / 340;
            int r  = i % 340;
            int yy = r / 34, xx = r % 34;
            int gy = by + yy - 1, gx = bx + xx - 1;
            float v = 0.f;
            if (gy >= 0 && gy < H && gx >= 0 && gx < W)
                v = inb[(size_t)(c0 + ci) * HW + gy * W + gx];
            sin_t[ci][yy][xx] = v;
        }
        __syncthreads();

#pragma unroll
        for (int ci = 0; ci < 4; ci++) {
            float r[9];
#pragma unroll
            for (int dy = 0; dy < 3; dy++)
#pragma unroll
                for (int dx = 0; dx < 3; dx++)
                    r[dy * 3 + dx] = sin_t[ci][ty + dy][tx + dx];
#pragma unroll
            for (int k = 0; k < 9; k++) {
                const float4* wv =
                    reinterpret_cast<const float4*>(&sw[(ci * 9 + k) * COUT_PB]);
#pragma unroll
                for (int j = 0; j < COUT_PB / 4; j++) {
                    float4 w4 = wv[j];
                    acc[j * 4 + 0] += r[k] * w4.x;
                    acc[j * 4 + 1] += r[k] * w4.y;
                    acc[j * 4 + 2] += r[k] * w4.z;
                    acc[j * 4 + 3] += r[k] * w4.w;
                }
            }
        }
    }

    size_t obase = ((size_t)b * COUT + co0) * HW + (size_t)(by + ty) * W + (bx + tx);
#pragma unroll
    for (int i = 0; i < COUT_PB; i++) {
        float v = acc[i];
        if (ACT == 0)      v = fmaxf(v, 0.f);
        else if (ACT == 1) v = 1.f / (1.f + expf(-v));
        out[obase + (size_t)i * HW] = v;
    }
}

// ---------------- launch -----------------------------------------------------
extern "C" void kernel_launch(void* const* d_in, const int* in_sizes, int n_in,
                              void* d_out, int out_size)
{
    const float* ft0 = (const float*)d_in[0];
    const float* ft1 = (const float*)d_in[1];
    const float* gup = (const float*)d_in[2];
    const float* dd  = (const float*)d_in[3];
    const float* ca  = (const float*)d_in[4];
    const float* cb  = (const float*)d_in[5];
    const float* fw1 = (const float*)d_in[6];
    const float* fb1 = (const float*)d_in[7];
    const float* fw2 = (const float*)d_in[8];
    const float* fb2 = (const float*)d_in[9];
    const float* fw3 = (const float*)d_in[10];
    const float* fb3 = (const float*)d_in[11];
    const float* dw1 = (const float*)d_in[12];
    const float* db1 = (const float*)d_in[13];
    const float* dw2 = (const float*)d_in[14];
    const float* db2 = (const float*)d_in[15];
    const float* dw3 = (const float*)d_in[16];
    const float* db3 = (const float*)d_in[17];

    float* out        = (float*)d_out;
    float* out_fusion = out;                                  // (4,64,256,256)
    float* out_den    = out + (size_t)B * 64 * HW;            // (4,64,256,256)
    float* out_gamma  = out + (size_t)2 * B * 64 * HW;        // (4,4,256,256)
    float* out_sigma  = out_gamma + (size_t)B * 4 * HW;       // (4,4,256,256)

    float *fin, *buf0, *buf1, *din;
    cudaGetSymbolAddress((void**)&fin,  g_fin);
    cudaGetSymbolAddress((void**)&buf0, g_buf0);
    cudaGetSymbolAddress((void**)&buf1, g_buf1);
    cudaGetSymbolAddress((void**)&din,  g_din);

    const int ew_threads = 256;
    const int ew_blocks  = (B * P4 + ew_threads - 1) / ew_threads;

    prep_kernel<<<ew_blocks, ew_threads>>>(ft0, ft1, gup, ca, cb, fin);

    dim3 blk(256);
    conv3x3_kernel<24, 64, 16, 0><<<dim3(8, 32, 16), blk>>>(fin,  fw1, fb1, buf0);
    conv3x3_kernel<64, 64, 16, 0><<<dim3(8, 32, 16), blk>>>(buf0, fw2, fb2, buf1);
    conv3x3_kernel<64,  4,  4, 1><<<dim3(8, 32,  4), blk>>>(buf1, fw3, fb3, out_gamma);

    fuse_kernel<<<ew_blocks, ew_threads>>>(ft0, ft1, dd, ca, cb,
                                           out_gamma, out_fusion, out_sigma, din);

    conv3x3_kernel<100, 64, 16, 0><<<dim3(8, 32, 16), blk>>>(din,  dw1, db1, buf0);
    conv3x3_kernel< 64, 64, 16, 0><<<dim3(8, 32, 16), blk>>>(buf0, dw2, db2, buf1);
    conv3x3_kernel< 64, 64, 16, 2><<<dim3(8, 32, 16), blk>>>(buf1, dw3, db3, out_den);
}

// round 7
// speedup vs baseline: 1.5353x; 1.5353x over previous
#include <cuda_runtime.h>
#include <cstdint>
#include <math.h>

#define H 256
#define W 256
#define B 4
#define HW 65536
#define P4 16384   // HW / 4

// ---------------- scratch (static device globals; no runtime allocation) ----
__device__ float g_fin [B * 24  * HW];   //  24 MB
__device__ float g_buf0[B * 64  * HW];   //  64 MB
__device__ float g_buf1[B * 64  * HW];   //  64 MB
__device__ float g_din [B * 104 * HW];   // 104 MB

// ---------------- PTX helpers ------------------------------------------------
__device__ __forceinline__ uint32_t smem_u32(const void* p) {
    uint32_t a;
    asm("{ .reg .u64 t; cvta.to.shared.u64 t, %1; cvt.u32.u64 %0, t; }"
        : "=r"(a) : "l"(p));
    return a;
}
#define CP_ASYNC4(dst, src, sz) \
    asm volatile("cp.async.ca.shared.global [%0], [%1], 4, %2;" \
        :: "r"(dst), "l"(src), "r"(sz))
#define CP_COMMIT() asm volatile("cp.async.commit_group;" ::: "memory")
#define CP_WAIT0()  asm volatile("cp.async.wait_group 0;" ::: "memory")
#define CP_WAIT1()  asm volatile("cp.async.wait_group 1;" ::: "memory")

__device__ __forceinline__ void mma16n8k8(float* c, const uint32_t* a,
                                          uint32_t b0, uint32_t b1) {
    asm volatile(
        "mma.sync.aligned.m16n8k8.row.col.f32.tf32.tf32.f32 "
        "{%0,%1,%2,%3}, {%4,%5,%6,%7}, {%8,%9}, {%0,%1,%2,%3};"
        : "+f"(c[0]), "+f"(c[1]), "+f"(c[2]), "+f"(c[3])
        : "r"(a[0]), "r"(a[1]), "r"(a[2]), "r"(a[3]), "r"(b0), "r"(b1));
}
// tf32 hi/lo split: hi = rn_tf32(x), lo = x - hi (3xTF32 scheme)
__device__ __forceinline__ void split_tf32(float x, uint32_t& hi, uint32_t& lo) {
    float h;
    asm("cvt.rna.tf32.f32 %0, %1;" : "=f"(h) : "f"(x));
    hi = __float_as_uint(h);
    lo = __float_as_uint(x - h);
}

// ================= 3xTF32 mma.sync implicit-GEMM 3x3 conv ====================
// Block: 256 threads (8 warps) = one full image row, all COUT channels.
// Warp w: pixels [w*32, w*32+32) as two m16 tiles; N covered by NT8 n8-tiles.
// K loop: cin-chunks of 8 (outer, cp.async double-buffered) x 9 taps (inner).
// Each logical MMA is 3 tf32 MMAs: ah*bh + al*bh + ah*bl  (~fp32 accuracy).
//
// smem input tile per chunk: [8ch][3rows][264], plane stride 792 words
//   -> A-frag banks (24c + 8dy + x) % 32 : conflict-free.
// smem weights per chunk: [tap*8+k][72] -> B-frag banks (8k+n)%32 : bijective.
// ACT: 0=relu 1=sigmoid 2=none.
template <int CIN, int CINP, int COUT, int NT8, int ACT>
__global__ void __launch_bounds__(256, 2)
conv_mma(const float* __restrict__ in, const float* __restrict__ wgt,
         const float* __restrict__ bias, float* __restrict__ out)
{
    constexpr int NC       = CINP / 8;
    constexpr int IN_WORDS = 8 * 3 * 264;   // 6336 per buffer
    constexpr int WT_WORDS = 72 * 72;       // 5184 per buffer

    extern __shared__ float sm[];
    float* in_s = sm;                        // 2 * IN_WORDS
    float* w_s  = sm + 2 * IN_WORDS;         // 2 * WT_WORDS
    const uint32_t in_u  = smem_u32(in_s);
    const uint32_t w_u   = smem_u32(w_s);

    const int tid  = threadIdx.x;
    const int wid  = tid >> 5;
    const int lane = tid & 31;
    const int y    = blockIdx.x;
    const int b    = blockIdx.y;

    // NOTE: batch stride is CINP (buffer stride), not CIN — R5 bug fix.
    const float* inb = in + (size_t)b * CINP * HW;

    float acc[2][NT8][4];
#pragma unroll
    for (int mi = 0; mi < 2; mi++)
#pragma unroll
        for (int nt = 0; nt < NT8; nt++)
#pragma unroll
            for (int e = 0; e < 4; e++) acc[mi][nt][e] = 0.f;

    // ---- chunk stager (cp.async) ----
    auto issue_chunk = [&](int ch, int buf) {
        const int c0 = ch * 8;
        const uint32_t ib = in_u + (uint32_t)buf * IN_WORDS * 4u;
#pragma unroll 1
        for (int i = tid; i < IN_WORDS; i += 256) {
            int xl   = i % 264;
            int rest = i / 264;
            int dy   = rest % 3;
            int c    = rest / 3;
            int gy   = y + dy - 1;
            int gx   = xl - 1;
            int ci   = c0 + c;
            bool v = (gy >= 0) & (gy < H) & (gx >= 0) & (gx < W) &
                     (CINP == CIN || ci < CIN);
            const float* src = inb + (v ? ((size_t)ci * HW + (size_t)gy * W + gx) : 0);
            CP_ASYNC4(ib + (uint32_t)(c * 792 + dy * 264 + xl) * 4u, src, v ? 4 : 0);
        }
        const uint32_t wb = w_u + (uint32_t)buf * WT_WORDS * 4u;
#pragma unroll 1
        for (int i = tid; i < 64 * 72; i += 256) {
            int co = i / 72;
            int r  = i % 72;          // = (ci_off)*9 + tap  (gmem-contiguous)
            int tap = r % 9;
            int k   = r / 9;
            bool v = (co < COUT) && (c0 * 9 + r < CIN * 9);
            const float* src = wgt + (v ? ((size_t)co * CIN * 9 + (size_t)c0 * 9 + r) : 0);
            CP_ASYNC4(wb + (uint32_t)((tap * 8 + k) * 72 + co) * 4u, src, v ? 4 : 0);
        }
    };

    issue_chunk(0, 0);
    CP_COMMIT();

    for (int ch = 0; ch < NC; ch++) {
        if (ch + 1 < NC) {
            issue_chunk(ch + 1, (ch + 1) & 1);
            CP_COMMIT();
            CP_WAIT1();
        } else {
            CP_WAIT0();
        }
        __syncthreads();

        const float* ibuf = in_s + (ch & 1) * IN_WORDS;
        const float* wbuf = w_s  + (ch & 1) * WT_WORDS;
        const int klo = lane & 3;            // k within chunk (0..3)
        const int r0  = lane >> 2;           // row-in-tile / n-in-tile

#pragma unroll
        for (int tap = 0; tap < 9; tap++) {
            const int dy = tap / 3, dx = tap % 3;
            uint32_t ah[2][4], al[2][4];
#pragma unroll
            for (int mi = 0; mi < 2; mi++) {
                const int xl = wid * 32 + mi * 16 + r0 + dx;
                const int base = klo * 792 + dy * 264 + xl;
                split_tf32(ibuf[base],                ah[mi][0], al[mi][0]);
                split_tf32(ibuf[base + 8],            ah[mi][1], al[mi][1]);
                split_tf32(ibuf[base + 4 * 792],      ah[mi][2], al[mi][2]);
                split_tf32(ibuf[base + 4 * 792 + 8],  ah[mi][3], al[mi][3]);
            }
            const int wrow = (tap * 8 + klo) * 72 + r0;
#pragma unroll
            for (int nt = 0; nt < NT8; nt++) {
                uint32_t bh0, bl0, bh1, bl1;
                split_tf32(wbuf[wrow + nt * 8],           bh0, bl0);
                split_tf32(wbuf[wrow + nt * 8 + 4 * 72],  bh1, bl1);
                uint32_t bl[2] = {bl0, bl1};
                uint32_t bhv[2] = {bh0, bh1};
                // hi*hi
                mma16n8k8(acc[0][nt], ah[0], bhv[0], bhv[1]);
                mma16n8k8(acc[1][nt], ah[1], bhv[0], bhv[1]);
                // lo*hi
                mma16n8k8(acc[0][nt], al[0], bhv[0], bhv[1]);
                mma16n8k8(acc[1][nt], al[1], bhv[0], bhv[1]);
                // hi*lo
                mma16n8k8(acc[0][nt], ah[0], bl[0], bl[1]);
                mma16n8k8(acc[1][nt], ah[1], bl[0], bl[1]);
            }
        }
        __syncthreads();
    }

    // ---- epilogue: bias + activation, NCHW stores ----
    const int r0 = lane >> 2;
#pragma unroll
    for (int nt = 0; nt < NT8; nt++) {
        const int co0 = nt * 8 + (lane & 3) * 2;
        if (COUT < 8 && co0 >= COUT) continue;   // gamma conv (COUT=4)
        const float bs0 = __ldg(&bias[co0]);
        const float bs1 = __ldg(&bias[co0 + 1]);
        float* o0 = out + ((size_t)b * COUT + co0) * HW + (size_t)y * W;
        float* o1 = o0 + HW;
#pragma unroll
        for (int mi = 0; mi < 2; mi++) {
            const int px = wid * 32 + mi * 16 + r0;
            float v0 = acc[mi][nt][0] + bs0;
            float v1 = acc[mi][nt][1] + bs1;
            float v2 = acc[mi][nt][2] + bs0;
            float v3 = acc[mi][nt][3] + bs1;
            if (ACT == 0) {
                v0 = fmaxf(v0, 0.f); v1 = fmaxf(v1, 0.f);
                v2 = fmaxf(v2, 0.f); v3 = fmaxf(v3, 0.f);
            } else if (ACT == 1) {
                v0 = 1.f / (1.f + __expf(-v0)); v1 = 1.f / (1.f + __expf(-v1));
                v2 = 1.f / (1.f + __expf(-v2)); v3 = 1.f / (1.f + __expf(-v3));
            }
            o0[px]     = v0;
            o1[px]     = v1;
            o0[px + 8] = v2;
            o1[px + 8] = v3;
        }
    }
}

// ---------------- elementwise: build fusion_in (24ch) -----------------------
__global__ void prep_kernel(const float* __restrict__ ft0,
                            const float* __restrict__ ft1,
                            const float* __restrict__ gup,
                            const float* __restrict__ ca,
                            const float* __restrict__ cb,
                            float* __restrict__ fin)
{
    int i = blockIdx.x * blockDim.x + threadIdx.x;
    if (i >= B * P4) return;
    int b = i >> 14;
    int p = i & (P4 - 1);
    const float4* f0 = (const float4*)(ft0 + (size_t)b * 64 * HW);
    const float4* f1 = (const float4*)(ft1 + (size_t)b * 64 * HW);
    const float4* gu = (const float4*)(gup + (size_t)b * 4 * HW);
    float4*       fo = (float4*)(fin + (size_t)b * 24 * HW);
    float a = *ca, bb = *cb;

#pragma unroll
    for (int c = 0; c < 16; c++) {
        float4 t0 = f0[(size_t)c * P4 + p];
        float4 t1 = f1[(size_t)c * P4 + p];
        float4 r;
        r.x = fabsf(t1.x - t0.x); r.y = fabsf(t1.y - t0.y);
        r.z = fabsf(t1.z - t0.z); r.w = fabsf(t1.w - t0.w);
        fo[(size_t)c * P4 + p] = r;
    }
#pragma unroll
    for (int c = 0; c < 4; c++)
        fo[(size_t)(16 + c) * P4 + p] = gu[(size_t)c * P4 + p];
#pragma unroll
    for (int c = 0; c < 4; c++) {
        float4 t1 = f1[(size_t)c * P4 + p];
        float4 r;
        r.x = fminf(fmaxf(t1.x, 0.f), 1.f) * a + bb;
        r.y = fminf(fmaxf(t1.y, 0.f), 1.f) * a + bb;
        r.z = fminf(fmaxf(t1.z, 0.f), 1.f) * a + bb;
        r.w = fminf(fmaxf(t1.w, 0.f), 1.f) * a + bb;
        fo[(size_t)(20 + c) * P4 + p] = r;
    }
}

// ---------------- elementwise: fusion_out / sigma / denoise_in --------------
__global__ void fuse_kernel(const float* __restrict__ ft0,
                            const float* __restrict__ ft1,
                            const float* __restrict__ dd,
                            const float* __restrict__ ca,
                            const float* __restrict__ cb,
                            const float* __restrict__ gamma,
                            float* __restrict__ out_fusion,
                            float* __restrict__ out_sigma,
                            float* __restrict__ din)
{
    int i = blockIdx.x * blockDim.x + threadIdx.x;
    if (i >= B * P4) return;
    int b = i >> 14;
    int p = i & (P4 - 1);
    const float4* f0 = (const float4*)(ft0 + (size_t)b * 64 * HW);
    const float4* f1 = (const float4*)(ft1 + (size_t)b * 64 * HW);
    const float4* dv = (const float4*)(dd  + (size_t)b * 16 * HW);
    const float4* gv = (const float4*)(gamma + (size_t)b * 4 * HW);
    float4* ofu = (float4*)(out_fusion + (size_t)b * 64 * HW);
    float4* osg = (float4*)(out_sigma  + (size_t)b * 4  * HW);
    float4* di  = (float4*)(din + (size_t)b * 104 * HW);
    float a = *ca, bb = *cb;

    float4 g[4];
#pragma unroll
    for (int c = 0; c < 4; c++) g[c] = gv[(size_t)c * P4 + p];

#pragma unroll
    for (int c = 0; c < 64; c++) {
        float4 t0 = f0[(size_t)c * P4 + p];
        float4 t1 = f1[(size_t)c * P4 + p];
        float4 gm = g[c >> 4];
        float4 r;
        r.x = t0.x + gm.x * (t1.x - t0.x);
        r.y = t0.y + gm.y * (t1.y - t0.y);
        r.z = t0.z + gm.z * (t1.z - t0.z);
        r.w = t0.w + gm.w * (t1.w - t0.w);
        ofu[(size_t)c * P4 + p] = r;
        di [(size_t)c * P4 + p] = r;
        if (c < 16) di[(size_t)(64 + c) * P4 + p] = t1;
    }
#pragma unroll
    for (int c = 0; c < 16; c++)
        di[(size_t)(80 + c) * P4 + p] = dv[(size_t)c * P4 + p];
#pragma unroll
    for (int c = 0; c < 4; c++) {
        float4 t0 = f0[(size_t)c * P4 + p];
        float4 t1 = f1[(size_t)c * P4 + p];
        float4 gm = g[c];
        float4 s;
        float s0, s1, om;
        s0 = fminf(fmaxf(t0.x,0.f),1.f)*a+bb; s1 = fminf(fmaxf(t1.x,0.f),1.f)*a+bb;
        om = 1.f - gm.x; s.x = om*om*s0 + gm.x*gm.x*s1;
        s0 = fminf(fmaxf(t0.y,0.f),1.f)*a+bb; s1 = fminf(fmaxf(t1.y,0.f),1.f)*a+bb;
        om = 1.f - gm.y; s.y = om*om*s0 + gm.y*gm.y*s1;
        s0 = fminf(fmaxf(t0.z,0.f),1.f)*a+bb; s1 = fminf(fmaxf(t1.z,0.f),1.f)*a+bb;
        om = 1.f - gm.z; s.z = om*om*s0 + gm.z*gm.z*s1;
        s0 = fminf(fmaxf(t0.w,0.f),1.f)*a+bb; s1 = fminf(fmaxf(t1.w,0.f),1.f)*a+bb;
        om = 1.f - gm.w; s.w = om*om*s0 + gm.w*gm.w*s1;
        osg[(size_t)c * P4 + p] = s;
        di [(size_t)(96 + c) * P4 + p] = s;
    }
}

// ---------------- launch -----------------------------------------------------
template <int CIN, int CINP, int COUT, int NT8, int ACT>
static inline void launch_conv(const float* in, const float* w, const float* bi,
                               float* out)
{
    constexpr int SMEM = (2 * (8 * 3 * 264) + 2 * (72 * 72)) * 4;  // 92160 B
    cudaFuncSetAttribute(conv_mma<CIN, CINP, COUT, NT8, ACT>,
                         cudaFuncAttributeMaxDynamicSharedMemorySize, SMEM);
    conv_mma<CIN, CINP, COUT, NT8, ACT><<<dim3(H, B), 256, SMEM>>>(in, w, bi, out);
}

extern "C" void kernel_launch(void* const* d_in, const int* in_sizes, int n_in,
                              void* d_out, int out_size)
{
    const float* ft0 = (const float*)d_in[0];
    const float* ft1 = (const float*)d_in[1];
    const float* gup = (const float*)d_in[2];
    const float* dd  = (const float*)d_in[3];
    const float* ca  = (const float*)d_in[4];
    const float* cb  = (const float*)d_in[5];
    const float* fw1 = (const float*)d_in[6];
    const float* fb1 = (const float*)d_in[7];
    const float* fw2 = (const float*)d_in[8];
    const float* fb2 = (const float*)d_in[9];
    const float* fw3 = (const float*)d_in[10];
    const float* fb3 = (const float*)d_in[11];
    const float* dw1 = (const float*)d_in[12];
    const float* db1 = (const float*)d_in[13];
    const float* dw2 = (const float*)d_in[14];
    const float* db2 = (const float*)d_in[15];
    const float* dw3 = (const float*)d_in[16];
    const float* db3 = (const float*)d_in[17];

    float* out        = (float*)d_out;
    float* out_fusion = out;                                  // (4,64,256,256)
    float* out_den    = out + (size_t)B * 64 * HW;            // (4,64,256,256)
    float* out_gamma  = out + (size_t)2 * B * 64 * HW;        // (4,4,256,256)
    float* out_sigma  = out_gamma + (size_t)B * 4 * HW;       // (4,4,256,256)

    float *fin, *buf0, *buf1, *din;
    cudaGetSymbolAddress((void**)&fin,  g_fin);
    cudaGetSymbolAddress((void**)&buf0, g_buf0);
    cudaGetSymbolAddress((void**)&buf1, g_buf1);
    cudaGetSymbolAddress((void**)&din,  g_din);

    const int ew_threads = 256;
    const int ew_blocks  = (B * P4 + ew_threads - 1) / ew_threads;

    prep_kernel<<<ew_blocks, ew_threads>>>(ft0, ft1, gup, ca, cb, fin);

    launch_conv< 24,  24, 64, 8, 0>(fin,  fw1, fb1, buf0);
    launch_conv< 64,  64, 64, 8, 0>(buf0, fw2, fb2, buf1);
    launch_conv< 64,  64,  4, 1, 1>(buf1, fw3, fb3, out_gamma);

    fuse_kernel<<<ew_blocks, ew_threads>>>(ft0, ft1, dd, ca, cb,
                                           out_gamma, out_fusion, out_sigma, din);

    launch_conv<100, 104, 64, 8, 0>(din,  dw1, db1, buf0);
    launch_conv< 64,  64, 64, 8, 0>(buf0, dw2, db2, buf1);
    launch_conv< 64,  64, 64, 8, 2>(buf1, dw3, db3, out_den);
}

// round 8
// speedup vs baseline: 2.7011x; 1.7594x over previous
#include <cuda_runtime.h>
#include <cstdint>
#include <math.h>

#define H 256
#define W 256
#define B 4
#define HW 65536

// ---------------- scratch (static device globals; no runtime allocation) ----
// Activation scratch: bf16x2 pair-packed, [hi | lo] halves.
// hi word at [(b*PAIRS + pair)*HW + pix], lo at +B*PAIRS*HW.
__device__ float g_fin [2 * B * 16 * HW];   // fusion_in,  16 pair-planes (12 real)
__device__ float g_bufA[2 * B * 32 * HW];   // conv1 out / conv4 out (32 pairs)
__device__ float g_bufB[2 * B * 32 * HW];   // conv2 out / conv5 out
__device__ float g_din [2 * B * 56 * HW];   // denoise_in, 56 pair-planes (50 real)
__device__ float g_wsc [57600 * 4];         // pre-split weights (uint4 units)

// ---------------- PTX helpers ------------------------------------------------
__device__ __forceinline__ uint32_t smem_u32(const void* p) {
    uint32_t a;
    asm("{ .reg .u64 t; cvta.to.shared.u64 t, %1; cvt.u32.u64 %0, t; }"
        : "=r"(a) : "l"(p));
    return a;
}
#define CP_ASYNC4(dst, src, sz) \
    asm volatile("cp.async.ca.shared.global [%0], [%1], 4, %2;" \
        :: "r"(dst), "l"(src), "r"(sz))
#define CP_ASYNC16(dst, src) \
    asm volatile("cp.async.ca.shared.global [%0], [%1], 16;" \
        :: "r"(dst), "l"(src))
#define CP_COMMIT() asm volatile("cp.async.commit_group;" ::: "memory")
#define CP_WAIT0()  asm volatile("cp.async.wait_group 0;" ::: "memory")
#define CP_WAIT1()  asm volatile("cp.async.wait_group 1;" ::: "memory")

__device__ __forceinline__ void mma_bf16(float* c, const uint32_t* a,
                                         uint32_t b0, uint32_t b1) {
    asm volatile(
        "mma.sync.aligned.m16n8k16.row.col.f32.bf16.bf16.f32 "
        "{%0,%1,%2,%3}, {%4,%5,%6,%7}, {%8,%9}, {%0,%1,%2,%3};"
        : "+f"(c[0]), "+f"(c[1]), "+f"(c[2]), "+f"(c[3])
        : "r"(a[0]), "r"(a[1]), "r"(a[2]), "r"(a[3]), "r"(b0), "r"(b1));
}
// pack (v0 -> low bf16, v1 -> high bf16) hi word + residual lo word
__device__ __forceinline__ void pack2(float v0, float v1,
                                      uint32_t& h, uint32_t& l) {
    asm("cvt.rn.bf16x2.f32 %0, %1, %2;" : "=r"(h) : "f"(v1), "f"(v0));
    float r0 = v0 - __uint_as_float(h << 16);
    float r1 = v1 - __uint_as_float(h & 0xffff0000u);
    asm("cvt.rn.bf16x2.f32 %0, %1, %2;" : "=r"(l) : "f"(r1), "f"(r0));
}

// ================ weight pre-split kernel ====================================
// Output per chunk (16 cin): [tap][co 0..63][tig 0..3] uint4 =
//   {bh(pair=tig), bl(tig), bh(tig+4), bl(tig+4)}, pair = 2 cin channels.
__global__ void split_w(const float* __restrict__ w, int CIN, int COUT,
                        int NCH, uint4* __restrict__ dst)
{
    int idx = blockIdx.x * blockDim.x + threadIdx.x;
    int total = NCH * 2304;
    if (idx >= total) return;
    int ch  = idx / 2304;
    int r   = idx % 2304;
    int tap = r / 256;
    int r2  = r % 256;
    int co  = r2 >> 2;
    int tig = r2 & 3;

    auto fetch = [&](int k) -> float {
        return (co < COUT && k < CIN) ? w[((size_t)co * CIN + k) * 9 + tap] : 0.f;
    };
    int k0 = ch * 16 + tig * 2;
    int k1 = ch * 16 + (tig + 4) * 2;
    uint32_t bh0, bl0, bh1, bl1;
    pack2(fetch(k0), fetch(k0 + 1), bh0, bl0);
    pack2(fetch(k1), fetch(k1 + 1), bh1, bl1);
    dst[idx] = make_uint4(bh0, bl0, bh1, bl1);
}

// ================ bf16-split mma.sync implicit-GEMM 3x3 conv =================
// Block 256 thr (8 warps) = one image row; warp w -> px [w*32, w*32+32).
// Chunk = 16 cin (8 pairs), cp.async double-buffered; 9 taps inner.
// A smem: [buf][hi/lo][pair 0..7][dy 0..2][x 0..263]  (plane stride 792 words)
// W smem: [buf][tap][co][tig] uint4 (LDS.128).
// Per (tap, nt): 6 MMAs: ah*bh, al*bh, ah*bl  x 2 m-tiles.
template <int PAIRS_ALLOC, int PAIRS_REAL, int COUT, int NT8, int ACT, int TO_F32>
__global__ void __launch_bounds__(256, 1)
conv_bf16(const uint32_t* __restrict__ inp, const uint4* __restrict__ wsc,
          const float* __restrict__ bias, float* __restrict__ outf,
          uint32_t* __restrict__ outs)
{
    constexpr int NC = PAIRS_ALLOC / 8;
    constexpr int AW = 12672;          // words per A buffer (6336 hi + 6336 lo)
    constexpr int WW = 9216;           // words per W buffer
    constexpr int PO = COUT / 2;

    extern __shared__ uint32_t sm[];
    uint32_t* smA = sm;                // [2][AW]
    uint32_t* smW = sm + 2 * AW;       // [2][WW]
    const uint32_t a_u = smem_u32(smA);
    const uint32_t w_u = smem_u32(smW);

    const int tid  = threadIdx.x;
    const int wid  = tid >> 5;
    const int lane = tid & 31;
    const int tig  = lane & 3;
    const int g    = lane >> 2;
    const int y    = blockIdx.x;
    const int b    = blockIdx.y;

    const size_t lo_off_in = (size_t)B * PAIRS_ALLOC * HW;

    float acc[2][NT8][4];
#pragma unroll
    for (int mi = 0; mi < 2; mi++)
#pragma unroll
        for (int nt = 0; nt < NT8; nt++)
#pragma unroll
            for (int e = 0; e < 4; e++) acc[mi][nt][e] = 0.f;

    auto issue_chunk = [&](int ch, int buf) {
#pragma unroll 1
        for (int i = tid; i < 6336; i += 256) {
            int xl   = i % 264;
            int rest = i / 264;
            int dy   = rest % 3;
            int pr   = rest / 3;
            int pair = ch * 8 + pr;
            int gy = y + dy - 1, gx = xl - 1;
            bool v = (gy >= 0) & (gy < H) & (gx >= 0) & (gx < W) &
                     (PAIRS_ALLOC == PAIRS_REAL || pair < PAIRS_REAL);
            size_t so = v ? ((size_t)(b * PAIRS_ALLOC + pair) * HW
                             + (size_t)gy * W + gx) : 0;
            uint32_t dH = a_u + (uint32_t)(buf * AW + pr * 792 + dy * 264 + xl) * 4u;
            CP_ASYNC4(dH,           inp + so,             v ? 4 : 0);
            CP_ASYNC4(dH + 6336*4u, inp + lo_off_in + so, v ? 4 : 0);
        }
        const uint4* ws = wsc + ch * 2304;
        const uint32_t wd = w_u + (uint32_t)(buf * WW) * 4u;
#pragma unroll 1
        for (int i = tid; i < 2304; i += 256)
            CP_ASYNC16(wd + (uint32_t)i * 16u, ws + i);
    };

    issue_chunk(0, 0);
    CP_COMMIT();

    for (int ch = 0; ch < NC; ch++) {
        if (ch + 1 < NC) {
            issue_chunk(ch + 1, (ch + 1) & 1);
            CP_COMMIT();
            CP_WAIT1();
        } else {
            CP_WAIT0();
        }
        __syncthreads();

        const uint32_t* Ah = smA + (ch & 1) * AW;
        const uint32_t* Al = Ah + 6336;
        const uint4*    Wb = (const uint4*)(smW + (ch & 1) * WW);
        const int xbase = wid * 32 + g;

#pragma unroll
        for (int tap = 0; tap < 9; tap++) {
            const int dy = tap / 3, dx = tap % 3;
            uint32_t aH[2][4], aL[2][4];
#pragma unroll
            for (int mi = 0; mi < 2; mi++) {
                const int base = dy * 264 + xbase + mi * 16 + dx;
                aH[mi][0] = Ah[tig * 792 + base];
                aH[mi][1] = Ah[tig * 792 + base + 8];
                aH[mi][2] = Ah[(tig + 4) * 792 + base];
                aH[mi][3] = Ah[(tig + 4) * 792 + base + 8];
                aL[mi][0] = Al[tig * 792 + base];
                aL[mi][1] = Al[tig * 792 + base + 8];
                aL[mi][2] = Al[(tig + 4) * 792 + base];
                aL[mi][3] = Al[(tig + 4) * 792 + base + 8];
            }
#pragma unroll
            for (int nt = 0; nt < NT8; nt++) {
                const int co = nt * 8 + g;
                uint4 w = Wb[tap * 256 + co * 4 + tig];
                mma_bf16(acc[0][nt], aH[0], w.x, w.z);   // hi*hi
                mma_bf16(acc[1][nt], aH[1], w.x, w.z);
                mma_bf16(acc[0][nt], aL[0], w.x, w.z);   // lo*hi
                mma_bf16(acc[1][nt], aL[1], w.x, w.z);
                mma_bf16(acc[0][nt], aH[0], w.y, w.w);   // hi*lo
                mma_bf16(acc[1][nt], aH[1], w.y, w.w);
            }
        }
        __syncthreads();
    }

    // ---- epilogue ----
#pragma unroll
    for (int nt = 0; nt < NT8; nt++) {
        const int co0 = nt * 8 + tig * 2;
        if (COUT < 8 && co0 >= COUT) continue;
        const float bs0 = __ldg(&bias[co0]);
        const float bs1 = __ldg(&bias[co0 + 1]);
#pragma unroll
        for (int mi = 0; mi < 2; mi++) {
            const int px = wid * 32 + mi * 16 + g;
            float v0 = acc[mi][nt][0] + bs0;
            float v1 = acc[mi][nt][1] + bs1;
            float v2 = acc[mi][nt][2] + bs0;
            float v3 = acc[mi][nt][3] + bs1;
            if (ACT == 0) {
                v0 = fmaxf(v0, 0.f); v1 = fmaxf(v1, 0.f);
                v2 = fmaxf(v2, 0.f); v3 = fmaxf(v3, 0.f);
            } else if (ACT == 1) {
                v0 = 1.f / (1.f + __expf(-v0)); v1 = 1.f / (1.f + __expf(-v1));
                v2 = 1.f / (1.f + __expf(-v2)); v3 = 1.f / (1.f + __expf(-v3));
            }
            if (TO_F32) {
                float* o0 = outf + ((size_t)b * COUT + co0) * HW + (size_t)y * W;
                float* o1 = o0 + HW;
                o0[px]     = v0;  o1[px]     = v1;
                o0[px + 8] = v2;  o1[px + 8] = v3;
            } else {
                const int pair = nt * 4 + tig;
                uint32_t h0, l0, h1, l1;
                pack2(v0, v1, h0, l0);
                pack2(v2, v3, h1, l1);
                size_t o = (size_t)(b * PO + pair) * HW + (size_t)y * W + px;
                size_t lo_off = (size_t)B * PO * HW;
                outs[o]            = h0;
                outs[o + 8]        = h1;
                outs[lo_off + o]   = l0;
                outs[lo_off + o + 8] = l1;
            }
        }
    }
}

// ---------------- prep: fusion_in -> pair-packed bf16 hi/lo ------------------
__global__ void prep_kernel(const float* __restrict__ ft0,
                            const float* __restrict__ ft1,
                            const float* __restrict__ gup,
                            const float* __restrict__ ca,
                            const float* __restrict__ cb,
                            uint32_t* __restrict__ fin)
{
    int p = blockIdx.x * blockDim.x + threadIdx.x;
    if (p >= B * HW) return;
    int b = p >> 16;
    int q = p & (HW - 1);
    const float* f0 = ft0 + (size_t)b * 64 * HW + q;
    const float* f1 = ft1 + (size_t)b * 64 * HW + q;
    const float* gu = gup + (size_t)b * 4 * HW + q;
    float a = *ca, bo = *cb;
    const size_t lo_off = (size_t)B * 16 * HW;

    auto st = [&](int pair, float v0, float v1) {
        uint32_t h, l;
        pack2(v0, v1, h, l);
        size_t o = (size_t)(b * 16 + pair) * HW + q;
        fin[o] = h;
        fin[lo_off + o] = l;
    };
#pragma unroll
    for (int i = 0; i < 8; i++) {
        float d0 = fabsf(f1[(size_t)(2 * i) * HW]     - f0[(size_t)(2 * i) * HW]);
        float d1 = fabsf(f1[(size_t)(2 * i + 1) * HW] - f0[(size_t)(2 * i + 1) * HW]);
        st(i, d0, d1);
    }
    st(8, gu[0], gu[(size_t)1 * HW]);
    st(9, gu[(size_t)2 * HW], gu[(size_t)3 * HW]);
#pragma unroll
    for (int i = 0; i < 2; i++) {
        float s0 = fminf(fmaxf(f1[(size_t)(2 * i) * HW],     0.f), 1.f) * a + bo;
        float s1 = fminf(fmaxf(f1[(size_t)(2 * i + 1) * HW], 0.f), 1.f) * a + bo;
        st(10 + i, s0, s1);
    }
}

// ---------------- fuse: fusion_out/sigma fp32 + denoise_in packed ------------
__global__ void fuse_kernel(const float* __restrict__ ft0,
                            const float* __restrict__ ft1,
                            const float* __restrict__ dd,
                            const float* __restrict__ ca,
                            const float* __restrict__ cb,
                            const float* __restrict__ gamma,
                            float* __restrict__ out_fusion,
                            float* __restrict__ out_sigma,
                            uint32_t* __restrict__ din)
{
    int p = blockIdx.x * blockDim.x + threadIdx.x;
    if (p >= B * HW) return;
    int b = p >> 16;
    int q = p & (HW - 1);
    const float* f0 = ft0 + (size_t)b * 64 * HW + q;
    const float* f1 = ft1 + (size_t)b * 64 * HW + q;
    const float* dv = dd  + (size_t)b * 16 * HW + q;
    const float* gv = gamma + (size_t)b * 4 * HW + q;
    float* ofu = out_fusion + (size_t)b * 64 * HW + q;
    float* osg = out_sigma  + (size_t)b * 4 * HW + q;
    float a = *ca, bo = *cb;
    const size_t lo_off = (size_t)B * 56 * HW;

    float g[4];
#pragma unroll
    for (int c = 0; c < 4; c++) g[c] = gv[(size_t)c * HW];

    auto st = [&](int pair, float v0, float v1) {
        uint32_t h, l;
        pack2(v0, v1, h, l);
        size_t o = (size_t)(b * 56 + pair) * HW + q;
        din[o] = h;
        din[lo_off + o] = l;
    };

#pragma unroll
    for (int c = 0; c < 32; c++) {               // fusion_out pairs 0..31
        float t00 = f0[(size_t)(2 * c) * HW],     t10 = f1[(size_t)(2 * c) * HW];
        float t01 = f0[(size_t)(2 * c + 1) * HW], t11 = f1[(size_t)(2 * c + 1) * HW];
        float gm = g[c >> 3];
        float r0 = t00 + gm * (t10 - t00);
        float r1 = t01 + gm * (t11 - t01);
        ofu[(size_t)(2 * c) * HW]     = r0;
        ofu[(size_t)(2 * c + 1) * HW] = r1;
        st(c, r0, r1);
    }
#pragma unroll
    for (int j = 0; j < 8; j++)                  // ll1 pairs 32..39
        st(32 + j, f1[(size_t)(2 * j) * HW], f1[(size_t)(2 * j + 1) * HW]);
#pragma unroll
    for (int j = 0; j < 8; j++)                  // denoise_down pairs 40..47
        st(40 + j, dv[(size_t)(2 * j) * HW], dv[(size_t)(2 * j + 1) * HW]);
    float sg[4];
#pragma unroll
    for (int c = 0; c < 4; c++) {                // sigma ch 0..3
        float s0 = fminf(fmaxf(f0[(size_t)c * HW], 0.f), 1.f) * a + bo;
        float s1 = fminf(fmaxf(f1[(size_t)c * HW], 0.f), 1.f) * a + bo;
        float om = 1.f - g[c];
        sg[c] = om * om * s0 + g[c] * g[c] * s1;
        osg[(size_t)c * HW] = sg[c];
    }
    st(48, sg[0], sg[1]);
    st(49, sg[2], sg[3]);
}

// ---------------- launch -----------------------------------------------------
template <int PA, int PR, int COUT, int NT8, int ACT, int TO_F32>
static inline void launch_conv(const uint32_t* in, const uint4* w,
                               const float* bi, float* of, uint32_t* os)
{
    constexpr int SMEM = (2 * 12672 + 2 * 9216) * 4;   // 175104 B
    cudaFuncSetAttribute(conv_bf16<PA, PR, COUT, NT8, ACT, TO_F32>,
                         cudaFuncAttributeMaxDynamicSharedMemorySize, SMEM);
    conv_bf16<PA, PR, COUT, NT8, ACT, TO_F32>
        <<<dim3(H, B), 256, SMEM>>>(in, w, bi, of, os);
}

extern "C" void kernel_launch(void* const* d_in, const int* in_sizes, int n_in,
                              void* d_out, int out_size)
{
    const float* ft0 = (const float*)d_in[0];
    const float* ft1 = (const float*)d_in[1];
    const float* gup = (const float*)d_in[2];
    const float* dd  = (const float*)d_in[3];
    const float* ca  = (const float*)d_in[4];
    const float* cb  = (const float*)d_in[5];
    const float* fw1 = (const float*)d_in[6];
    const float* fb1 = (const float*)d_in[7];
    const float* fw2 = (const float*)d_in[8];
    const float* fb2 = (const float*)d_in[9];
    const float* fw3 = (const float*)d_in[10];
    const float* fb3 = (const float*)d_in[11];
    const float* dw1 = (const float*)d_in[12];
    const float* db1 = (const float*)d_in[13];
    const float* dw2 = (const float*)d_in[14];
    const float* db2 = (const float*)d_in[15];
    const float* dw3 = (const float*)d_in[16];
    const float* db3 = (const float*)d_in[17];

    float* out        = (float*)d_out;
    float* out_fusion = out;
    float* out_den    = out + (size_t)B * 64 * HW;
    float* out_gamma  = out + (size_t)2 * B * 64 * HW;
    float* out_sigma  = out_gamma + (size_t)B * 4 * HW;

    float *fin_f, *bufA_f, *bufB_f, *din_f, *wsc_f;
    cudaGetSymbolAddress((void**)&fin_f,  g_fin);
    cudaGetSymbolAddress((void**)&bufA_f, g_bufA);
    cudaGetSymbolAddress((void**)&bufB_f, g_bufB);
    cudaGetSymbolAddress((void**)&din_f,  g_din);
    cudaGetSymbolAddress((void**)&wsc_f,  g_wsc);
    uint32_t* fin  = (uint32_t*)fin_f;
    uint32_t* bufA = (uint32_t*)bufA_f;
    uint32_t* bufB = (uint32_t*)bufB_f;
    uint32_t* din  = (uint32_t*)din_f;
    uint4*    wsc  = (uint4*)wsc_f;

    // weight pre-split (offsets in uint4 units)
    uint4* w1 = wsc;            // 2 chunks
    uint4* w2 = wsc + 4608;     // 4
    uint4* w3 = wsc + 13824;    // 4
    uint4* w4 = wsc + 23040;    // 7
    uint4* w5 = wsc + 39168;    // 4
    uint4* w6 = wsc + 48384;    // 4
    split_w<<<(2 * 2304 + 255) / 256, 256>>>(fw1,  24, 64, 2, w1);
    split_w<<<(4 * 2304 + 255) / 256, 256>>>(fw2,  64, 64, 4, w2);
    split_w<<<(4 * 2304 + 255) / 256, 256>>>(fw3,  64,  4, 4, w3);
    split_w<<<(7 * 2304 + 255) / 256, 256>>>(dw1, 100, 64, 7, w4);
    split_w<<<(4 * 2304 + 255) / 256, 256>>>(dw2,  64, 64, 4, w5);
    split_w<<<(4 * 2304 + 255) / 256, 256>>>(dw3,  64, 64, 4, w6);

    const int ew_blocks = (B * HW + 255) / 256;
    prep_kernel<<<ew_blocks, 256>>>(ft0, ft1, gup, ca, cb, fin);

    launch_conv<16, 12, 64, 8, 0, 0>(fin,  w1, fb1, nullptr, bufA);
    launch_conv<32, 32, 64, 8, 0, 0>(bufA, w2, fb2, nullptr, bufB);
    launch_conv<32, 32,  4, 1, 1, 1>(bufB, w3, fb3, out_gamma, nullptr);

    fuse_kernel<<<ew_blocks, 256>>>(ft0, ft1, dd, ca, cb,
                                    out_gamma, out_fusion, out_sigma, din);

    launch_conv<56, 50, 64, 8, 0, 0>(din,  w4, db1, nullptr, bufA);
    launch_conv<32, 32, 64, 8, 0, 0>(bufA, w5, db2, nullptr, bufB);
    launch_conv<32, 32, 64, 8, 2, 1>(bufB, w6, db3, out_den, nullptr);
}

// round 10
// speedup vs baseline: 3.6436x; 1.3489x over previous
#include <cuda_runtime.h>
#include <cuda_fp16.h>
#include <cstdint>
#include <math.h>

#define H 256
#define W 256
#define B 4
#define HW 65536

// ---------------- scratch (static device globals; no runtime allocation) ----
// Activation scratch: fp16x2 pair-packed, [hi | lo] halves.
__device__ float g_fin [2 * B * 16 * HW];   // fusion_in,  16 pair-planes (12 real)
__device__ float g_bufA[2 * B * 32 * HW];   // conv1/conv4 out (32 pairs)
__device__ float g_bufB[2 * B * 32 * HW];   // conv2/conv5 out
__device__ float g_din [2 * B * 56 * HW];   // denoise_in, 56 pair-planes (50 real)
__device__ float g_wsc [57600 * 2];         // pre-split weights (uint2 units)

// ---------------- PTX helpers ------------------------------------------------
__device__ __forceinline__ uint32_t smem_u32(const void* p) {
    uint32_t a;
    asm("{ .reg .u64 t; cvta.to.shared.u64 t, %1; cvt.u32.u64 %0, t; }"
        : "=r"(a) : "l"(p));
    return a;
}
#define CP_ASYNC4(dst, src, sz) \
    asm volatile("cp.async.ca.shared.global [%0], [%1], 4, %2;" \
        :: "r"(dst), "l"(src), "r"(sz))
#define CP_ASYNC8(dst, src) \
    asm volatile("cp.async.ca.shared.global [%0], [%1], 8;" \
        :: "r"(dst), "l"(src))
#define CP_COMMIT() asm volatile("cp.async.commit_group;" ::: "memory")
#define CP_WAIT0()  asm volatile("cp.async.wait_group 0;" ::: "memory")
#define CP_WAIT1()  asm volatile("cp.async.wait_group 1;" ::: "memory")

__device__ __forceinline__ void mma_f16(float* c, const uint32_t* a,
                                        uint32_t b0, uint32_t b1) {
    asm volatile(
        "mma.sync.aligned.m16n8k16.row.col.f32.f16.f16.f32 "
        "{%0,%1,%2,%3}, {%4,%5,%6,%7}, {%8,%9}, {%0,%1,%2,%3};"
        : "+f"(c[0]), "+f"(c[1]), "+f"(c[2]), "+f"(c[3])
        : "r"(a[0]), "r"(a[1]), "r"(a[2]), "r"(a[3]), "r"(b0), "r"(b1));
}
// activation pack: hi = f16x2(v0,v1), lo = f16x2 of residuals
__device__ __forceinline__ void packA(float v0, float v1,
                                      uint32_t& h, uint32_t& l) {
    __half2 hh = __floats2half2_rn(v0, v1);
    h = *reinterpret_cast<uint32_t*>(&hh);
    float r0 = v0 - __low2float(hh);
    float r1 = v1 - __high2float(hh);
    __half2 ll = __floats2half2_rn(r0, r1);
    l = *reinterpret_cast<uint32_t*>(&ll);
}
__device__ __forceinline__ uint32_t pack1(float v0, float v1) {
    __half2 hh = __floats2half2_rn(v0, v1);
    return *reinterpret_cast<uint32_t*>(&hh);
}

// ================ weight pre-split: ALL 6 convs in one launch ================
// Per chunk (16 cin): [tap][co 0..63][tig 0..3] uint2 = {b(pair tig), b(pair tig+4)}
__global__ void split_all(const float* __restrict__ w1, const float* __restrict__ w2,
                          const float* __restrict__ w3, const float* __restrict__ w4,
                          const float* __restrict__ w5, const float* __restrict__ w6,
                          uint2* __restrict__ dst)
{
    int idx = blockIdx.x * blockDim.x + threadIdx.x;
    if (idx >= 25 * 2304) return;
    int cg = idx / 2304;
    int r  = idx % 2304;
    const float* w; int CIN, COUT, ch;
    if      (cg < 2)  { w = w1; CIN = 24;  COUT = 64; ch = cg; }
    else if (cg < 6)  { w = w2; CIN = 64;  COUT = 64; ch = cg - 2; }
    else if (cg < 10) { w = w3; CIN = 64;  COUT = 4;  ch = cg - 6; }
    else if (cg < 17) { w = w4; CIN = 100; COUT = 64; ch = cg - 10; }
    else if (cg < 21) { w = w5; CIN = 64;  COUT = 64; ch = cg - 17; }
    else              { w = w6; CIN = 64;  COUT = 64; ch = cg - 21; }
    int tap = r / 256;
    int co  = (r % 256) >> 2;
    int tig = r & 3;
    auto f = [&](int k) -> float {
        return (co < COUT && k < CIN) ? w[((size_t)co * CIN + k) * 9 + tap] : 0.f;
    };
    int k0 = ch * 16 + tig * 2;
    int k1 = ch * 16 + (tig + 4) * 2;
    dst[idx] = make_uint2(pack1(f(k0), f(k0 + 1)), pack1(f(k1), f(k1 + 1)));
}

// ================ fp16 2-term mma.sync implicit-GEMM 3x3 conv ================
// Block 128 thr (4 warps) = half image row (128 px); warp w -> px [w*32,+32).
// Chunk = 16 cin (8 pairs), cp.async double-buffered; 9 taps inner.
// A smem: [buf][hi/lo][pair 0..7][dy 0..2][x 0..135] (plane stride 408 words).
// W smem: [buf][tap][co][tig] uint2.
// Per (tap, nt, mi): 2 MMAs: ah*b + al*b.
template <int PA, int PR, int COUT, int NT8, int ACT, int TO_F32, int FUSE>
__global__ void __launch_bounds__(128, 2)
conv_f16(const uint32_t* __restrict__ inp, const uint2* __restrict__ wsc,
         const float* __restrict__ bias, float* __restrict__ outf,
         uint32_t* __restrict__ outs,
         const float* __restrict__ ft0, const float* __restrict__ ft1,
         const float* __restrict__ dd, const float* __restrict__ ca,
         const float* __restrict__ cb, float* __restrict__ out_fusion,
         float* __restrict__ out_sigma, uint32_t* __restrict__ din)
{
    constexpr int NC   = PA / 8;
    constexpr int AWH  = 8 * 408;          // 3264 words, hi half
    constexpr int AW   = 2 * AWH;          // 6528 words per buffer
    constexpr int WWu  = 4608;             // words per W buffer (2304 uint2)
    constexpr int PO   = (COUT >= 8) ? COUT / 2 : 2;

    extern __shared__ uint32_t sm[];
    uint32_t* smA = sm;                    // [2][AW]
    uint32_t* smW = sm + 2 * AW;           // [2][WWu]
    const uint32_t a_u = smem_u32(smA);
    const uint32_t w_u = smem_u32(smW);

    const int tid  = threadIdx.x;
    const int wid  = tid >> 5;
    const int lane = tid & 31;
    const int tig  = lane & 3;
    const int g    = lane >> 2;
    const int y    = blockIdx.x >> 1;
    const int x0   = (blockIdx.x & 1) * 128;
    const int b    = blockIdx.y;

    const size_t loIn = (size_t)B * PA * HW;

    float acc[2][NT8][4];
#pragma unroll
    for (int mi = 0; mi < 2; mi++)
#pragma unroll
        for (int nt = 0; nt < NT8; nt++)
#pragma unroll
            for (int e = 0; e < 4; e++) acc[mi][nt][e] = 0.f;

    auto issue_chunk = [&](int ch, int buf) {
#pragma unroll 1
        for (int i = tid; i < 3264; i += 128) {
            int xl   = i % 136;
            int rest = i / 136;
            int dy   = rest % 3;
            int pr   = rest / 3;
            int pair = ch * 8 + pr;
            int gy = y + dy - 1, gx = x0 + xl - 1;
            bool v = (gy >= 0) & (gy < H) & (gx >= 0) & (gx < W) &
                     (PA == PR || pair < PR);
            size_t so = v ? ((size_t)(b * PA + pair) * HW + (size_t)gy * W + gx) : 0;
            uint32_t dA = a_u + (uint32_t)(buf * AW + pr * 408 + dy * 136 + xl) * 4u;
            CP_ASYNC4(dA,             inp + so,        v ? 4 : 0);
            CP_ASYNC4(dA + AWH * 4u,  inp + loIn + so, v ? 4 : 0);
        }
        const uint2* ws = wsc + ch * 2304;
        const uint32_t wd = w_u + (uint32_t)(buf * WWu) * 4u;
#pragma unroll 1
        for (int i = tid; i < 2304; i += 128)
            CP_ASYNC8(wd + (uint32_t)i * 8u, ws + i);
    };

    issue_chunk(0, 0);
    CP_COMMIT();

    for (int ch = 0; ch < NC; ch++) {
        if (ch + 1 < NC) {
            issue_chunk(ch + 1, (ch + 1) & 1);
            CP_COMMIT();
            CP_WAIT1();
        } else {
            CP_WAIT0();
        }
        __syncthreads();

        const uint32_t* Ah = smA + (ch & 1) * AW;
        const uint32_t* Al = Ah + AWH;
        const uint2*    Wb = (const uint2*)(smW + (ch & 1) * WWu);
        const int xbase = wid * 32 + g;

#pragma unroll
        for (int tap = 0; tap < 9; tap++) {
            const int dy = tap / 3, dx = tap % 3;
            uint32_t aH[2][4], aL[2][4];
#pragma unroll
            for (int mi = 0; mi < 2; mi++) {
                const int base = dy * 136 + xbase + mi * 16 + dx;
                aH[mi][0] = Ah[tig * 408 + base];
                aH[mi][1] = Ah[tig * 408 + base + 8];
                aH[mi][2] = Ah[(tig + 4) * 408 + base];
                aH[mi][3] = Ah[(tig + 4) * 408 + base + 8];
                aL[mi][0] = Al[tig * 408 + base];
                aL[mi][1] = Al[tig * 408 + base + 8];
                aL[mi][2] = Al[(tig + 4) * 408 + base];
                aL[mi][3] = Al[(tig + 4) * 408 + base + 8];
            }
#pragma unroll
            for (int nt = 0; nt < NT8; nt++) {
                uint2 w = Wb[tap * 256 + (nt * 8 + g) * 4 + tig];
                mma_f16(acc[0][nt], aH[0], w.x, w.y);
                mma_f16(acc[1][nt], aH[1], w.x, w.y);
                mma_f16(acc[0][nt], aL[0], w.x, w.y);
                mma_f16(acc[1][nt], aL[1], w.x, w.y);
            }
        }
        __syncthreads();
    }

    // ---- epilogue ----
    float* gsm = (float*)smA;              // reused (all reads done)
#pragma unroll
    for (int nt = 0; nt < NT8; nt++) {
        const int co0 = nt * 8 + tig * 2;
        if (COUT < 8 && co0 >= COUT) continue;
        const float bs0 = __ldg(&bias[co0]);
        const float bs1 = __ldg(&bias[co0 + 1]);
#pragma unroll
        for (int mi = 0; mi < 2; mi++) {
            const int px = wid * 32 + mi * 16 + g;
            float v0 = acc[mi][nt][0] + bs0;
            float v1 = acc[mi][nt][1] + bs1;
            float v2 = acc[mi][nt][2] + bs0;
            float v3 = acc[mi][nt][3] + bs1;
            if (ACT == 0) {
                v0 = fmaxf(v0, 0.f); v1 = fmaxf(v1, 0.f);
                v2 = fmaxf(v2, 0.f); v3 = fmaxf(v3, 0.f);
            } else if (ACT == 1) {
                v0 = 1.f / (1.f + __expf(-v0)); v1 = 1.f / (1.f + __expf(-v1));
                v2 = 1.f / (1.f + __expf(-v2)); v3 = 1.f / (1.f + __expf(-v3));
            }
            if (TO_F32) {
                float* o0 = outf + ((size_t)b * COUT + co0) * HW
                            + (size_t)y * W + x0;
                float* o1 = o0 + HW;
                o0[px]     = v0;  o1[px]     = v1;
                o0[px + 8] = v2;  o1[px + 8] = v3;
            } else {
                const int pair = nt * 4 + tig;
                uint32_t h0, l0, h1, l1;
                packA(v0, v1, h0, l0);
                packA(v2, v3, h1, l1);
                size_t o = (size_t)(b * PO + pair) * HW + (size_t)y * W + x0 + px;
                size_t loO = (size_t)B * PO * HW;
                outs[o]           = h0;
                outs[o + 8]       = h1;
                outs[loO + o]     = l0;
                outs[loO + o + 8] = l1;
            }
            if (FUSE) {
                gsm[co0 * 132 + px]           = v0;
                gsm[(co0 + 1) * 132 + px]     = v1;
                gsm[co0 * 132 + px + 8]       = v2;
                gsm[(co0 + 1) * 132 + px + 8] = v3;
            }
        }
    }

    // ---- fused elementwise stage (conv3 only): fusion_out / sigma / din ----
    if (FUSE) {
        __syncthreads();
        const int q = (int)y * W + x0 + tid;
        const float* f0 = ft0 + (size_t)b * 64 * HW + q;
        const float* f1 = ft1 + (size_t)b * 64 * HW + q;
        const float* dv = dd  + (size_t)b * 16 * HW + q;
        float* ofu = out_fusion + (size_t)b * 64 * HW + q;
        float* osg = out_sigma  + (size_t)b * 4 * HW + q;
        const float a = *ca, bo = *cb;
        const size_t loD = (size_t)B * 56 * HW;

        float g4[4];
#pragma unroll
        for (int c = 0; c < 4; c++) g4[c] = gsm[c * 132 + tid];

        auto st = [&](int pair, float v0, float v1) {
            uint32_t h, l;
            packA(v0, v1, h, l);
            size_t o = (size_t)(b * 56 + pair) * HW + q;
            din[o] = h;
            din[loD + o] = l;
        };
#pragma unroll
        for (int c = 0; c < 32; c++) {
            float t00 = f0[(size_t)(2 * c) * HW],     t10 = f1[(size_t)(2 * c) * HW];
            float t01 = f0[(size_t)(2 * c + 1) * HW], t11 = f1[(size_t)(2 * c + 1) * HW];
            float gm = g4[c >> 3];
            float r0 = t00 + gm * (t10 - t00);
            float r1 = t01 + gm * (t11 - t01);
            ofu[(size_t)(2 * c) * HW]     = r0;
            ofu[(size_t)(2 * c + 1) * HW] = r1;
            st(c, r0, r1);
        }
#pragma unroll
        for (int j = 0; j < 8; j++)
            st(32 + j, f1[(size_t)(2 * j) * HW], f1[(size_t)(2 * j + 1) * HW]);
#pragma unroll
        for (int j = 0; j < 8; j++)
            st(40 + j, dv[(size_t)(2 * j) * HW], dv[(size_t)(2 * j + 1) * HW]);
        float sg[4];
#pragma unroll
        for (int c = 0; c < 4; c++) {
            float s0 = fminf(fmaxf(f0[(size_t)c * HW], 0.f), 1.f) * a + bo;
            float s1 = fminf(fmaxf(f1[(size_t)c * HW], 0.f), 1.f) * a + bo;
            float om = 1.f - g4[c];
            sg[c] = om * om * s0 + g4[c] * g4[c] * s1;
            osg[(size_t)c * HW] = sg[c];
        }
        st(48, sg[0], sg[1]);
        st(49, sg[2], sg[3]);
    }
}

// ---------------- prep: fusion_in -> pair-packed fp16 hi/lo ------------------
__global__ void prep_kernel(const float* __restrict__ ft0,
                            const float* __restrict__ ft1,
                            const float* __restrict__ gup,
                            const float* __restrict__ ca,
                            const float* __restrict__ cb,
                            uint32_t* __restrict__ fin)
{
    int p = blockIdx.x * blockDim.x + threadIdx.x;
    if (p >= B * HW) return;
    int b = p >> 16;
    int q = p & (HW - 1);
    const float* f0 = ft0 + (size_t)b * 64 * HW + q;
    const float* f1 = ft1 + (size_t)b * 64 * HW + q;
    const float* gu = gup + (size_t)b * 4 * HW + q;
    float a = *ca, bo = *cb;
    const size_t lo_off = (size_t)B * 16 * HW;

    auto st = [&](int pair, float v0, float v1) {
        uint32_t h, l;
        packA(v0, v1, h, l);
        size_t o = (size_t)(b * 16 + pair) * HW + q;
        fin[o] = h;
        fin[lo_off + o] = l;
    };
#pragma unroll
    for (int i = 0; i < 8; i++) {
        float d0 = fabsf(f1[(size_t)(2 * i) * HW]     - f0[(size_t)(2 * i) * HW]);
        float d1 = fabsf(f1[(size_t)(2 * i + 1) * HW] - f0[(size_t)(2 * i + 1) * HW]);
        st(i, d0, d1);
    }
    st(8, gu[0], gu[(size_t)1 * HW]);
    st(9, gu[(size_t)2 * HW], gu[(size_t)3 * HW]);
#pragma unroll
    for (int i = 0; i < 2; i++) {
        float s0 = fminf(fmaxf(f1[(size_t)(2 * i) * HW],     0.f), 1.f) * a + bo;
        float s1 = fminf(fmaxf(f1[(size_t)(2 * i + 1) * HW], 0.f), 1.f) * a + bo;
        st(10 + i, s0, s1);
    }
}

// ---------------- launch -----------------------------------------------------
template <int PA, int PR, int COUT, int NT8, int ACT, int TO_F32, int FUSE>
static inline void launch_conv(const uint32_t* in, const uint2* w,
                               const float* bi, float* of, uint32_t* os,
                               const float* ft0 = nullptr, const float* ft1 = nullptr,
                               const float* dd = nullptr, const float* ca = nullptr,
                               const float* cb = nullptr, float* ofu = nullptr,
                               float* osg = nullptr, uint32_t* din = nullptr)
{
    constexpr int SMEM = (2 * 6528 + 2 * 4608) * 4;   // 89088 B
    cudaFuncSetAttribute(conv_f16<PA, PR, COUT, NT8, ACT, TO_F32, FUSE>,
                         cudaFuncAttributeMaxDynamicSharedMemorySize, SMEM);
    conv_f16<PA, PR, COUT, NT8, ACT, TO_F32, FUSE>
        <<<dim3(2 * H, B), 128, SMEM>>>(in, w, bi, of, os,
                                        ft0, ft1, dd, ca, cb, ofu, osg, din);
}

extern "C" void kernel_launch(void* const* d_in, const int* in_sizes, int n_in,
                              void* d_out, int out_size)
{
    const float* ft0 = (const float*)d_in[0];
    const float* ft1 = (const float*)d_in[1];
    const float* gup = (const float*)d_in[2];
    const float* dd  = (const float*)d_in[3];
    const float* ca  = (const float*)d_in[4];
    const float* cb  = (const float*)d_in[5];
    const float* fw1 = (const float*)d_in[6];
    const float* fb1 = (const float*)d_in[7];
    const float* fw2 = (const float*)d_in[8];
    const float* fb2 = (const float*)d_in[9];
    const float* fw3 = (const float*)d_in[10];
    const float* fb3 = (const float*)d_in[11];
    const float* dw1 = (const float*)d_in[12];
    const float* db1 = (const float*)d_in[13];
    const float* dw2 = (const float*)d_in[14];
    const float* db2 = (const float*)d_in[15];
    const float* dw3 = (const float*)d_in[16];
    const float* db3 = (const float*)d_in[17];

    float* out        = (float*)d_out;
    float* out_fusion = out;
    float* out_den    = out + (size_t)B * 64 * HW;
    float* out_gamma  = out + (size_t)2 * B * 64 * HW;
    float* out_sigma  = out_gamma + (size_t)B * 4 * HW;

    float *fin_f, *bufA_f, *bufB_f, *din_f, *wsc_f;
    cudaGetSymbolAddress((void**)&fin_f,  g_fin);
    cudaGetSymbolAddress((void**)&bufA_f, g_bufA);
    cudaGetSymbolAddress((void**)&bufB_f, g_bufB);
    cudaGetSymbolAddress((void**)&din_f,  g_din);
    cudaGetSymbolAddress((void**)&wsc_f,  g_wsc);
    uint32_t* fin  = (uint32_t*)fin_f;
    uint32_t* bufA = (uint32_t*)bufA_f;
    uint32_t* bufB = (uint32_t*)bufB_f;
    uint32_t* din  = (uint32_t*)din_f;
    uint2*    wsc  = (uint2*)wsc_f;

    // chunk offsets (x2304 uint2): w1@0(2) w2@2(4) w3@6(4) w4@10(7) w5@17(4) w6@21(4)
    split_all<<<(25 * 2304 + 255) / 256, 256>>>(fw1, fw2, fw3, dw1, dw2, dw3, wsc);

    prep_kernel<<<(B * HW + 255) / 256, 256>>>(ft0, ft1, gup, ca, cb, fin);

    launch_conv<16, 12, 64, 8, 0, 0, 0>(fin,  wsc,              fb1, nullptr, bufA);
    launch_conv<32, 32, 64, 8, 0, 0, 0>(bufA, wsc + 2  * 2304,  fb2, nullptr, bufB);
    launch_conv<32, 32,  4, 1, 1, 1, 1>(bufB, wsc + 6  * 2304,  fb3, out_gamma, nullptr,
                                        ft0, ft1, dd, ca, cb,
                                        out_fusion, out_sigma, din);
    launch_conv<56, 50, 64, 8, 0, 0, 0>(din,  wsc + 10 * 2304,  db1, nullptr, bufA);
    launch_conv<32, 32, 64, 8, 0, 0, 0>(bufA, wsc + 17 * 2304,  db2, nullptr, bufB);
    launch_conv<32, 32, 64, 8, 2, 1, 0>(bufB, wsc + 21 * 2304,  db3, out_den, nullptr);
}

// round 11
// speedup vs baseline: 5.6072x; 1.5389x over previous
#include <cuda_runtime.h>
#include <cuda_fp16.h>
#include <cstdint>
#include <math.h>

#define H 256
#define W 256
#define B 4
#define HW 65536

// ---------------- scratch (static device globals; no runtime allocation) ----
// Activation scratch: fp16x2 pair-packed, [hi | lo] plane halves.
__device__ float g_fin [2 * B * 16 * HW];   // fusion_in,  16 pair-planes (12 real)
__device__ float g_bufA[2 * B * 32 * HW];   // conv1/conv4 out (32 pairs)
__device__ float g_bufB[2 * B * 32 * HW];   // conv2/conv5 out
__device__ float g_din [2 * B * 56 * HW];   // denoise_in, 56 pair-planes (50 real)
__device__ float g_wsc [57600 * 2];         // pre-split weights (uint2 units)

// ---------------- PTX helpers ------------------------------------------------
__device__ __forceinline__ uint32_t smem_u32(const void* p) {
    uint32_t a;
    asm("{ .reg .u64 t; cvta.to.shared.u64 t, %1; cvt.u32.u64 %0, t; }"
        : "=r"(a) : "l"(p));
    return a;
}
#define CP_ASYNC8(dst, src) \
    asm volatile("cp.async.ca.shared.global [%0], [%1], 8;" \
        :: "r"(dst), "l"(src))
#define CP_ASYNC16Z(dst, src, sz) \
    asm volatile("cp.async.cg.shared.global [%0], [%1], 16, %2;" \
        :: "r"(dst), "l"(src), "r"(sz))
#define CP_COMMIT() asm volatile("cp.async.commit_group;" ::: "memory")
#define CP_WAIT0()  asm volatile("cp.async.wait_group 0;" ::: "memory")
#define CP_WAIT1()  asm volatile("cp.async.wait_group 1;" ::: "memory")

__device__ __forceinline__ void mma_f16(float* c, const uint32_t* a,
                                        uint32_t b0, uint32_t b1) {
    asm volatile(
        "mma.sync.aligned.m16n8k16.row.col.f32.f16.f16.f32 "
        "{%0,%1,%2,%3}, {%4,%5,%6,%7}, {%8,%9}, {%0,%1,%2,%3};"
        : "+f"(c[0]), "+f"(c[1]), "+f"(c[2]), "+f"(c[3])
        : "r"(a[0]), "r"(a[1]), "r"(a[2]), "r"(a[3]), "r"(b0), "r"(b1));
}
// activation pack: hi = f16x2(v0,v1), lo = f16x2 of residuals
__device__ __forceinline__ void packA(float v0, float v1,
                                      uint32_t& h, uint32_t& l) {
    __half2 hh = __floats2half2_rn(v0, v1);
    h = *reinterpret_cast<uint32_t*>(&hh);
    float r0 = v0 - __low2float(hh);
    float r1 = v1 - __high2float(hh);
    __half2 ll = __floats2half2_rn(r0, r1);
    l = *reinterpret_cast<uint32_t*>(&ll);
}
__device__ __forceinline__ uint32_t pack1(float v0, float v1) {
    __half2 hh = __floats2half2_rn(v0, v1);
    return *reinterpret_cast<uint32_t*>(&hh);
}

// ================ weight pre-split: ALL 6 convs in one launch ================
// Per chunk (16 cin): [tap][co 0..63][tig 0..3] uint2 = {b(pair tig), b(pair tig+4)}
__global__ void split_all(const float* __restrict__ w1, const float* __restrict__ w2,
                          const float* __restrict__ w3, const float* __restrict__ w4,
                          const float* __restrict__ w5, const float* __restrict__ w6,
                          uint2* __restrict__ dst)
{
    int idx = blockIdx.x * blockDim.x + threadIdx.x;
    if (idx >= 25 * 2304) return;
    int cg = idx / 2304;
    int r  = idx % 2304;
    const float* w; int CIN, COUT, ch;
    if      (cg < 2)  { w = w1; CIN = 24;  COUT = 64; ch = cg; }
    else if (cg < 6)  { w = w2; CIN = 64;  COUT = 64; ch = cg - 2; }
    else if (cg < 10) { w = w3; CIN = 64;  COUT = 4;  ch = cg - 6; }
    else if (cg < 17) { w = w4; CIN = 100; COUT = 64; ch = cg - 10; }
    else if (cg < 21) { w = w5; CIN = 64;  COUT = 64; ch = cg - 17; }
    else              { w = w6; CIN = 64;  COUT = 64; ch = cg - 21; }
    int tap = r / 256;
    int co  = (r % 256) >> 2;
    int tig = r & 3;
    auto f = [&](int k) -> float {
        return (co < COUT && k < CIN) ? w[((size_t)co * CIN + k) * 9 + tap] : 0.f;
    };
    int k0 = ch * 16 + tig * 2;
    int k1 = ch * 16 + (tig + 4) * 2;
    dst[idx] = make_uint2(pack1(f(k0), f(k0 + 1)), pack1(f(k1), f(k1 + 1)));
}

// ================ fp16 2-term mma.sync implicit-GEMM 3x3 conv ================
// Block 128 thr (4 warps) = half image row (128 px); warp w -> px [w*32,+32).
// Chunk = 16 cin (8 pairs); A double-buffered (16B cp.async), W single-buffered.
// A smem: [buf][hi/lo][pair][dy][140]  pair stride 440 words (==24 mod 32:
//   banks {0,24,16,8}+g conflict-free). Word xl' <-> gx = x0 + xl' - 4.
// W smem: [tap][co][tig] uint2 (single buffer, restaged per chunk).
// Per tap: 16 hi-MMAs then 16 lo-MMAs (breaks accumulator RAW chains).
template <int PA, int PR, int COUT, int NT8, int ACT, int TO_F32, int FUSE>
__global__ void __launch_bounds__(128, 3)
conv_f16(const uint32_t* __restrict__ inp, const uint2* __restrict__ wsc,
         const float* __restrict__ bias, float* __restrict__ outf,
         uint32_t* __restrict__ outs,
         const float* __restrict__ ft0, const float* __restrict__ ft1,
         const float* __restrict__ dd, const float* __restrict__ ca,
         const float* __restrict__ cb, float* __restrict__ out_fusion,
         float* __restrict__ out_sigma, uint32_t* __restrict__ din)
{
    constexpr int NC   = PA / 8;
    constexpr int PSTR = 440;              // pair stride (words)
    constexpr int AWH  = 8 * PSTR;         // 3520 words per hi/lo half
    constexpr int AW   = 2 * AWH;          // 7040 words per A buffer
    constexpr int WWu  = 4608;             // words in W buffer (2304 uint2)
    constexpr int PO   = (COUT >= 8) ? COUT / 2 : 2;

    extern __shared__ uint32_t sm[];
    uint32_t* smA = sm;                    // [2][AW]
    uint32_t* smW = sm + 2 * AW;           // [WWu]
    const uint32_t a_u = smem_u32(smA);
    const uint32_t w_u = smem_u32(smW);

    const int tid  = threadIdx.x;
    const int wid  = tid >> 5;
    const int lane = tid & 31;
    const int tig  = lane & 3;
    const int g    = lane >> 2;
    const int y    = blockIdx.x >> 1;
    const int x0   = (blockIdx.x & 1) * 128;
    const int b    = blockIdx.y;

    const size_t loIn = (size_t)B * PA * HW;

    float acc[2][NT8][4];
#pragma unroll
    for (int mi = 0; mi < 2; mi++)
#pragma unroll
        for (int nt = 0; nt < NT8; nt++)
#pragma unroll
            for (int e = 0; e < 4; e++) acc[mi][nt][e] = 0.f;

    // ---- A stager: 16B vectors; 24 rows x 35 groups per chunk ----
    auto issue_A = [&](int ch, int buf) {
#pragma unroll 1
        for (int i = tid; i < 840; i += 128) {
            int row = i / 35;              // pr*3 + dy
            int j   = i % 35;
            int dy  = row % 3;
            int pr  = row / 3;
            int pair = ch * 8 + pr;
            int gy  = y + dy - 1;
            int gx0 = x0 - 4 + 4 * j;
            bool v = (gy >= 0) & (gy < H) & (gx0 >= 0) & (gx0 < W) &
                     (PA == PR || pair < PR);
            size_t so = v ? ((size_t)(b * PA + pair) * HW + (size_t)gy * W + gx0) : 0;
            uint32_t dA = a_u + (uint32_t)(buf * AW + pr * PSTR + dy * 140 + 4 * j) * 4u;
            CP_ASYNC16Z(dA,            inp + so,        v ? 16 : 0);
            CP_ASYNC16Z(dA + AWH * 4u, inp + loIn + so, v ? 16 : 0);
        }
    };
    auto issue_W = [&](int ch) {
        const uint2* ws = wsc + ch * 2304;
#pragma unroll 1
        for (int i = tid; i < 2304; i += 128)
            CP_ASYNC8(w_u + (uint32_t)i * 8u, ws + i);
    };

    issue_A(0, 0);
    CP_COMMIT();

    for (int ch = 0; ch < NC; ch++) {
        issue_W(ch);
        CP_COMMIT();
        if (ch + 1 < NC) {
            issue_A(ch + 1, (ch + 1) & 1);
            CP_COMMIT();
            CP_WAIT1();                    // A(ch) + W(ch) complete
        } else {
            CP_WAIT0();
        }
        __syncthreads();

        const uint32_t* Ah = smA + (ch & 1) * AW;
        const uint32_t* Al = Ah + AWH;
        const uint2*    Wb = (const uint2*)smW;
        const int xbase = wid * 32 + g + 3;    // +3: dst shift of A rows

#pragma unroll
        for (int tap = 0; tap < 9; tap++) {
            const int dy = tap / 3, dx = tap % 3;
            uint32_t aH[2][4], aL[2][4];
#pragma unroll
            for (int mi = 0; mi < 2; mi++) {
                const int base = dy * 140 + xbase + mi * 16 + dx;
                aH[mi][0] = Ah[tig * PSTR + base];
                aH[mi][1] = Ah[tig * PSTR + base + 8];
                aH[mi][2] = Ah[(tig + 4) * PSTR + base];
                aH[mi][3] = Ah[(tig + 4) * PSTR + base + 8];
                aL[mi][0] = Al[tig * PSTR + base];
                aL[mi][1] = Al[tig * PSTR + base + 8];
                aL[mi][2] = Al[(tig + 4) * PSTR + base];
                aL[mi][3] = Al[(tig + 4) * PSTR + base + 8];
            }
            uint2 wreg[NT8];
#pragma unroll
            for (int nt = 0; nt < NT8; nt++)
                wreg[nt] = Wb[tap * 256 + (nt * 8 + g) * 4 + tig];
#pragma unroll
            for (int nt = 0; nt < NT8; nt++) {       // hi pass
                mma_f16(acc[0][nt], aH[0], wreg[nt].x, wreg[nt].y);
                mma_f16(acc[1][nt], aH[1], wreg[nt].x, wreg[nt].y);
            }
#pragma unroll
            for (int nt = 0; nt < NT8; nt++) {       // lo pass
                mma_f16(acc[0][nt], aL[0], wreg[nt].x, wreg[nt].y);
                mma_f16(acc[1][nt], aL[1], wreg[nt].x, wreg[nt].y);
            }
        }
        __syncthreads();
    }

    // ---- epilogue ----
    float* gsm = (float*)smA;              // reused (all reads done)
#pragma unroll
    for (int nt = 0; nt < NT8; nt++) {
        const int co0 = nt * 8 + tig * 2;
        if (COUT < 8 && co0 >= COUT) continue;
        const float bs0 = __ldg(&bias[co0]);
        const float bs1 = __ldg(&bias[co0 + 1]);
#pragma unroll
        for (int mi = 0; mi < 2; mi++) {
            const int px = wid * 32 + mi * 16 + g;
            float v0 = acc[mi][nt][0] + bs0;
            float v1 = acc[mi][nt][1] + bs1;
            float v2 = acc[mi][nt][2] + bs0;
            float v3 = acc[mi][nt][3] + bs1;
            if (ACT == 0) {
                v0 = fmaxf(v0, 0.f); v1 = fmaxf(v1, 0.f);
                v2 = fmaxf(v2, 0.f); v3 = fmaxf(v3, 0.f);
            } else if (ACT == 1) {
                v0 = 1.f / (1.f + __expf(-v0)); v1 = 1.f / (1.f + __expf(-v1));
                v2 = 1.f / (1.f + __expf(-v2)); v3 = 1.f / (1.f + __expf(-v3));
            }
            if (TO_F32) {
                float* o0 = outf + ((size_t)b * COUT + co0) * HW
                            + (size_t)y * W + x0;
                float* o1 = o0 + HW;
                o0[px]     = v0;  o1[px]     = v1;
                o0[px + 8] = v2;  o1[px + 8] = v3;
            } else {
                const int pair = nt * 4 + tig;
                uint32_t h0, l0, h1, l1;
                packA(v0, v1, h0, l0);
                packA(v2, v3, h1, l1);
                size_t o = (size_t)(b * PO + pair) * HW + (size_t)y * W + x0 + px;
                size_t loO = (size_t)B * PO * HW;
                outs[o]           = h0;
                outs[o + 8]       = h1;
                outs[loO + o]     = l0;
                outs[loO + o + 8] = l1;
            }
            if (FUSE) {
                gsm[co0 * 132 + px]           = v0;
                gsm[(co0 + 1) * 132 + px]     = v1;
                gsm[co0 * 132 + px + 8]       = v2;
                gsm[(co0 + 1) * 132 + px + 8] = v3;
            }
        }
    }

    // ---- fused elementwise stage (conv3 only): fusion_out / sigma / din ----
    if (FUSE) {
        __syncthreads();
        const int q = (int)y * W + x0 + tid;
        const float* f0 = ft0 + (size_t)b * 64 * HW + q;
        const float* f1 = ft1 + (size_t)b * 64 * HW + q;
        const float* dv = dd  + (size_t)b * 16 * HW + q;
        float* ofu = out_fusion + (size_t)b * 64 * HW + q;
        float* osg = out_sigma  + (size_t)b * 4 * HW + q;
        const float a = *ca, bo = *cb;
        const size_t loD = (size_t)B * 56 * HW;

        float g4[4];
#pragma unroll
        for (int c = 0; c < 4; c++) g4[c] = gsm[c * 132 + tid];

        auto st = [&](int pair, float v0, float v1) {
            uint32_t h, l;
            packA(v0, v1, h, l);
            size_t o = (size_t)(b * 56 + pair) * HW + q;
            din[o] = h;
            din[loD + o] = l;
        };
#pragma unroll
        for (int c = 0; c < 32; c++) {
            float t00 = f0[(size_t)(2 * c) * HW],     t10 = f1[(size_t)(2 * c) * HW];
            float t01 = f0[(size_t)(2 * c + 1) * HW], t11 = f1[(size_t)(2 * c + 1) * HW];
            float gm = g4[c >> 3];
            float r0 = t00 + gm * (t10 - t00);
            float r1 = t01 + gm * (t11 - t01);
            ofu[(size_t)(2 * c) * HW]     = r0;
            ofu[(size_t)(2 * c + 1) * HW] = r1;
            st(c, r0, r1);
        }
#pragma unroll
        for (int j = 0; j < 8; j++)
            st(32 + j, f1[(size_t)(2 * j) * HW], f1[(size_t)(2 * j + 1) * HW]);
#pragma unroll
        for (int j = 0; j < 8; j++)
            st(40 + j, dv[(size_t)(2 * j) * HW], dv[(size_t)(2 * j + 1) * HW]);
        float sg[4];
#pragma unroll
        for (int c = 0; c < 4; c++) {
            float s0 = fminf(fmaxf(f0[(size_t)c * HW], 0.f), 1.f) * a + bo;
            float s1 = fminf(fmaxf(f1[(size_t)c * HW], 0.f), 1.f) * a + bo;
            float om = 1.f - g4[c];
            sg[c] = om * om * s0 + g4[c] * g4[c] * s1;
            osg[(size_t)c * HW] = sg[c];
        }
        st(48, sg[0], sg[1]);
        st(49, sg[2], sg[3]);
    }
}

// ---------------- prep: fusion_in -> pair-packed fp16 hi/lo ------------------
__global__ void prep_kernel(const float* __restrict__ ft0,
                            const float* __restrict__ ft1,
                            const float* __restrict__ gup,
                            const float* __restrict__ ca,
                            const float* __restrict__ cb,
                            uint32_t* __restrict__ fin)
{
    int p = blockIdx.x * blockDim.x + threadIdx.x;
    if (p >= B * HW) return;
    int b = p >> 16;
    int q = p & (HW - 1);
    const float* f0 = ft0 + (size_t)b * 64 * HW + q;
    const float* f1 = ft1 + (size_t)b * 64 * HW + q;
    const float* gu = gup + (size_t)b * 4 * HW + q;
    float a = *ca, bo = *cb;
    const size_t lo_off = (size_t)B * 16 * HW;

    auto st = [&](int pair, float v0, float v1) {
        uint32_t h, l;
        packA(v0, v1, h, l);
        size_t o = (size_t)(b * 16 + pair) * HW + q;
        fin[o] = h;
        fin[lo_off + o] = l;
    };
#pragma unroll
    for (int i = 0; i < 8; i++) {
        float d0 = fabsf(f1[(size_t)(2 * i) * HW]     - f0[(size_t)(2 * i) * HW]);
        float d1 = fabsf(f1[(size_t)(2 * i + 1) * HW] - f0[(size_t)(2 * i + 1) * HW]);
        st(i, d0, d1);
    }
    st(8, gu[0], gu[(size_t)1 * HW]);
    st(9, gu[(size_t)2 * HW], gu[(size_t)3 * HW]);
#pragma unroll
    for (int i = 0; i < 2; i++) {
        float s0 = fminf(fmaxf(f1[(size_t)(2 * i) * HW],     0.f), 1.f) * a + bo;
        float s1 = fminf(fmaxf(f1[(size_t)(2 * i + 1) * HW], 0.f), 1.f) * a + bo;
        st(10 + i, s0, s1);
    }
}

// ---------------- launch -----------------------------------------------------
template <int PA, int PR, int COUT, int NT8, int ACT, int TO_F32, int FUSE>
static inline void launch_conv(const uint32_t* in, const uint2* w,
                               const float* bi, float* of, uint32_t* os,
                               const float* ft0 = nullptr, const float* ft1 = nullptr,
                               const float* dd = nullptr, const float* ca = nullptr,
                               const float* cb = nullptr, float* ofu = nullptr,
                               float* osg = nullptr, uint32_t* din = nullptr)
{
    constexpr int SMEM = (2 * 7040 + 4608) * 4;   // 74752 B -> 3 CTAs/SM
    cudaFuncSetAttribute(conv_f16<PA, PR, COUT, NT8, ACT, TO_F32, FUSE>,
                         cudaFuncAttributeMaxDynamicSharedMemorySize, SMEM);
    conv_f16<PA, PR, COUT, NT8, ACT, TO_F32, FUSE>
        <<<dim3(2 * H, B), 128, SMEM>>>(in, w, bi, of, os,
                                        ft0, ft1, dd, ca, cb, ofu, osg, din);
}

extern "C" void kernel_launch(void* const* d_in, const int* in_sizes, int n_in,
                              void* d_out, int out_size)
{
    const float* ft0 = (const float*)d_in[0];
    const float* ft1 = (const float*)d_in[1];
    const float* gup = (const float*)d_in[2];
    const float* dd  = (const float*)d_in[3];
    const float* ca  = (const float*)d_in[4];
    const float* cb  = (const float*)d_in[5];
    const float* fw1 = (const float*)d_in[6];
    const float* fb1 = (const float*)d_in[7];
    const float* fw2 = (const float*)d_in[8];
    const float* fb2 = (const float*)d_in[9];
    const float* fw3 = (const float*)d_in[10];
    const float* fb3 = (const float*)d_in[11];
    const float* dw1 = (const float*)d_in[12];
    const float* db1 = (const float*)d_in[13];
    const float* dw2 = (const float*)d_in[14];
    const float* db2 = (const float*)d_in[15];
    const float* dw3 = (const float*)d_in[16];
    const float* db3 = (const float*)d_in[17];

    float* out        = (float*)d_out;
    float* out_fusion = out;
    float* out_den    = out + (size_t)B * 64 * HW;
    float* out_gamma  = out + (size_t)2 * B * 64 * HW;
    float* out_sigma  = out_gamma + (size_t)B * 4 * HW;

    float *fin_f, *bufA_f, *bufB_f, *din_f, *wsc_f;
    cudaGetSymbolAddress((void**)&fin_f,  g_fin);
    cudaGetSymbolAddress((void**)&bufA_f, g_bufA);
    cudaGetSymbolAddress((void**)&bufB_f, g_bufB);
    cudaGetSymbolAddress((void**)&din_f,  g_din);
    cudaGetSymbolAddress((void**)&wsc_f,  g_wsc);
    uint32_t* fin  = (uint32_t*)fin_f;
    uint32_t* bufA = (uint32_t*)bufA_f;
    uint32_t* bufB = (uint32_t*)bufB_f;
    uint32_t* din  = (uint32_t*)din_f;
    uint2*    wsc  = (uint2*)wsc_f;

    // chunk offsets (x2304 uint2): w1@0(2) w2@2(4) w3@6(4) w4@10(7) w5@17(4) w6@21(4)
    split_all<<<(25 * 2304 + 255) / 256, 256>>>(fw1, fw2, fw3, dw1, dw2, dw3, wsc);

    prep_kernel<<<(B * HW + 255) / 256, 256>>>(ft0, ft1, gup, ca, cb, fin);

    launch_conv<16, 12, 64, 8, 0, 0, 0>(fin,  wsc,              fb1, nullptr, bufA);
    launch_conv<32, 32, 64, 8, 0, 0, 0>(bufA, wsc + 2  * 2304,  fb2, nullptr, bufB);
    launch_conv<32, 32,  4, 1, 1, 1, 1>(bufB, wsc + 6  * 2304,  fb3, out_gamma, nullptr,
                                        ft0, ft1, dd, ca, cb,
                                        out_fusion, out_sigma, din);
    launch_conv<56, 50, 64, 8, 0, 0, 0>(din,  wsc + 10 * 2304,  db1, nullptr, bufA);
    launch_conv<32, 32, 64, 8, 0, 0, 0>(bufA, wsc + 17 * 2304,  db2, nullptr, bufB);
    launch_conv<32, 32, 64, 8, 2, 1, 0>(bufB, wsc + 21 * 2304,  db3, out_den, nullptr);
}

// round 13
// speedup vs baseline: 6.1810x; 1.1023x over previous
#include <cuda_runtime.h>
#include <cuda_fp16.h>
#include <cstdint>
#include <math.h>

#define H 256
#define W 256
#define B 4
#define HW 65536

// ---------------- scratch (static device globals; no runtime allocation) ----
// Activation scratch: fp16x2 pair-packed, [hi | lo] plane halves.
__device__ float g_fin [2 * B * 16 * HW];   // fusion_in,  16 pair-planes (12 real)
__device__ float g_bufA[2 * B * 32 * HW];   // conv1/conv4 out (32 pairs)
__device__ float g_bufB[2 * B * 32 * HW];   // conv2/conv5 out
__device__ float g_din [2 * B * 56 * HW];   // denoise_in, 56 pair-planes (50 real)
__device__ float g_wsc [57600 * 2];         // pre-split weights (uint2 units)

// ---------------- PTX helpers ------------------------------------------------
__device__ __forceinline__ uint32_t smem_u32(const void* p) {
    uint32_t a;
    asm("{ .reg .u64 t; cvta.to.shared.u64 t, %1; cvt.u32.u64 %0, t; }"
        : "=r"(a) : "l"(p));
    return a;
}
#define CP_ASYNC8(dst, src) \
    asm volatile("cp.async.ca.shared.global [%0], [%1], 8;" \
        :: "r"(dst), "l"(src))
#define CP_ASYNC16Z(dst, src, sz) \
    asm volatile("cp.async.cg.shared.global [%0], [%1], 16, %2;" \
        :: "r"(dst), "l"(src), "r"(sz))
#define CP_COMMIT() asm volatile("cp.async.commit_group;" ::: "memory")
#define CP_WAIT0()  asm volatile("cp.async.wait_group 0;" ::: "memory")
#define CP_WAIT1()  asm volatile("cp.async.wait_group 1;" ::: "memory")

__device__ __forceinline__ void mma_f16(float* c, const uint32_t* a,
                                        uint32_t b0, uint32_t b1) {
    asm volatile(
        "mma.sync.aligned.m16n8k16.row.col.f32.f16.f16.f32 "
        "{%0,%1,%2,%3}, {%4,%5,%6,%7}, {%8,%9}, {%0,%1,%2,%3};"
        : "+f"(c[0]), "+f"(c[1]), "+f"(c[2]), "+f"(c[3])
        : "r"(a[0]), "r"(a[1]), "r"(a[2]), "r"(a[3]), "r"(b0), "r"(b1));
}
// activation pack: hi = f16x2(v0,v1), lo = f16x2 of residuals
__device__ __forceinline__ void packA(float v0, float v1,
                                      uint32_t& h, uint32_t& l) {
    __half2 hh = __floats2half2_rn(v0, v1);
    h = *reinterpret_cast<uint32_t*>(&hh);
    float r0 = v0 - __low2float(hh);
    float r1 = v1 - __high2float(hh);
    __half2 ll = __floats2half2_rn(r0, r1);
    l = *reinterpret_cast<uint32_t*>(&ll);
}
__device__ __forceinline__ uint32_t pack1(float v0, float v1) {
    __half2 hh = __floats2half2_rn(v0, v1);
    return *reinterpret_cast<uint32_t*>(&hh);
}

// ================ weight pre-split: ALL 6 convs in one launch ================
// Per chunk (16 cin): [tap][co 0..63][tig 0..3] uint2 = {b(pair tig), b(pair tig+4)}
__global__ void split_all(const float* __restrict__ w1, const float* __restrict__ w2,
                          const float* __restrict__ w3, const float* __restrict__ w4,
                          const float* __restrict__ w5, const float* __restrict__ w6,
                          uint2* __restrict__ dst)
{
    int idx = blockIdx.x * blockDim.x + threadIdx.x;
    if (idx >= 25 * 2304) return;
    int cg = idx / 2304;
    int r  = idx % 2304;
    const float* w; int CIN, COUT, ch;
    if      (cg < 2)  { w = w1; CIN = 24;  COUT = 64; ch = cg; }
    else if (cg < 6)  { w = w2; CIN = 64;  COUT = 64; ch = cg - 2; }
    else if (cg < 10) { w = w3; CIN = 64;  COUT = 4;  ch = cg - 6; }
    else if (cg < 17) { w = w4; CIN = 100; COUT = 64; ch = cg - 10; }
    else if (cg < 21) { w = w5; CIN = 64;  COUT = 64; ch = cg - 17; }
    else              { w = w6; CIN = 64;  COUT = 64; ch = cg - 21; }
    int tap = r / 256;
    int co  = (r % 256) >> 2;
    int tig = r & 3;
    auto f = [&](int k) -> float {
        return (co < COUT && k < CIN) ? w[((size_t)co * CIN + k) * 9 + tap] : 0.f;
    };
    int k0 = ch * 16 + tig * 2;
    int k1 = ch * 16 + (tig + 4) * 2;
    dst[idx] = make_uint2(pack1(f(k0), f(k0 + 1)), pack1(f(k1), f(k1 + 1)));
}

// ================ fp16 2-term mma.sync implicit-GEMM 3x3 conv ================
// Block 256 thr (8 warps) = 2 rows x 128 px; warp w -> row (w>>2),
// px [(w&3)*32, +32). Chunk = 16 cin (8 pairs); A double-buffered (16B
// cp.async over 4 input rows, halo amortized), W single-buffered.
// A smem: [buf][hi/lo][pair][trow 0..3][140], pair stride 568 (==24 mod 32:
//   LDS banks {0,24,16,8}+g conflict-free). Word xl' <-> gx = x0 + xl' - 4.
// W smem: [tap][co][tig] uint2 (restaged per chunk).
// Per tap: 16 hi-MMAs then 16 lo-MMAs per warp (breaks accumulator RAW).
template <int PA, int PR, int COUT, int NT8, int ACT, int TO_F32, int FUSE>
__global__ void __launch_bounds__(256, 2)
conv_f16(const uint32_t* __restrict__ inp, const uint2* __restrict__ wsc,
         const float* __restrict__ bias, float* __restrict__ outf,
         uint32_t* __restrict__ outs,
         const float* __restrict__ ft0, const float* __restrict__ ft1,
         const float* __restrict__ dd, const float* __restrict__ ca,
         const float* __restrict__ cb, float* __restrict__ out_fusion,
         float* __restrict__ out_sigma, uint32_t* __restrict__ din)
{
    constexpr int NC   = PA / 8;
    constexpr int PSTR = 568;              // pair stride (4 rows x 140, padded)
    constexpr int AWH  = 8 * PSTR;         // 4544 words per hi/lo half
    constexpr int AW   = 2 * AWH;          // 9088 words per A buffer
    constexpr int PO   = (COUT >= 8) ? COUT / 2 : 2;

    extern __shared__ uint32_t sm[];
    uint32_t* smA = sm;                    // [2][AW]
    uint32_t* smW = sm + 2 * AW;           // [4608]
    const uint32_t a_u = smem_u32(smA);
    const uint32_t w_u = smem_u32(smW);

    const int tid  = threadIdx.x;
    const int wid  = tid >> 5;
    const int lane = tid & 31;
    const int tig  = lane & 3;
    const int g    = lane >> 2;
    const int wr   = wid >> 2;             // warp's row within block (0/1)
    const int wx   = (wid & 3) * 32;       // warp's px base within 128
    const int y0   = (blockIdx.x >> 1) * 2;
    const int x0   = (blockIdx.x & 1) * 128;
    const int b    = blockIdx.y;

    const size_t loIn = (size_t)B * PA * HW;

    float acc[2][NT8][4];
#pragma unroll
    for (int mi = 0; mi < 2; mi++)
#pragma unroll
        for (int nt = 0; nt < NT8; nt++)
#pragma unroll
            for (int e = 0; e < 4; e++) acc[mi][nt][e] = 0.f;

    // ---- A stager: 16B vectors; 8 pairs x 4 rows x 35 groups per chunk ----
    auto issue_A = [&](int ch, int buf) {
#pragma unroll 1
        for (int i = tid; i < 1120; i += 256) {
            int j    = i % 35;
            int row  = i / 35;             // pr*4 + tr
            int tr   = row & 3;
            int pr   = row >> 2;
            int pair = ch * 8 + pr;
            int gy   = y0 + tr - 1;
            int gx0  = x0 - 4 + 4 * j;
            bool v = (gy >= 0) & (gy < H) & (gx0 >= 0) & (gx0 < W) &
                     (PA == PR || pair < PR);
            size_t so = v ? ((size_t)(b * PA + pair) * HW + (size_t)gy * W + gx0) : 0;
            uint32_t dA = a_u + (uint32_t)(buf * AW + pr * PSTR + tr * 140 + 4 * j) * 4u;
            CP_ASYNC16Z(dA,            inp + so,        v ? 16 : 0);
            CP_ASYNC16Z(dA + AWH * 4u, inp + loIn + so, v ? 16 : 0);
        }
    };
    auto issue_W = [&](int ch) {
        const uint2* ws = wsc + ch * 2304;
#pragma unroll 1
        for (int i = tid; i < 2304; i += 256)
            CP_ASYNC8(w_u + (uint32_t)i * 8u, ws + i);
    };

    issue_A(0, 0);
    CP_COMMIT();

    for (int ch = 0; ch < NC; ch++) {
        issue_W(ch);
        CP_COMMIT();
        if (ch + 1 < NC) {
            issue_A(ch + 1, (ch + 1) & 1);
            CP_COMMIT();
            CP_WAIT1();                    // A(ch) + W(ch) complete
        } else {
            CP_WAIT0();
        }
        __syncthreads();

        const uint32_t* Ah = smA + (ch & 1) * AW;
        const uint32_t* Al = Ah + AWH;
        const uint2*    Wb = (const uint2*)smW;
        const int xbase = wx + g + 3;      // +3: dst shift of A rows

#pragma unroll
        for (int tap = 0; tap < 9; tap++) {
            const int dy = tap / 3, dx = tap % 3;
            const int trow = wr + dy;      // tile row 0..3
            uint32_t aH[2][4], aL[2][4];
#pragma unroll
            for (int mi = 0; mi < 2; mi++) {
                const int base = trow * 140 + xbase + mi * 16 + dx;
                aH[mi][0] = Ah[tig * PSTR + base];
                aH[mi][1] = Ah[tig * PSTR + base + 8];
                aH[mi][2] = Ah[(tig + 4) * PSTR + base];
                aH[mi][3] = Ah[(tig + 4) * PSTR + base + 8];
                aL[mi][0] = Al[tig * PSTR + base];
                aL[mi][1] = Al[tig * PSTR + base + 8];
                aL[mi][2] = Al[(tig + 4) * PSTR + base];
                aL[mi][3] = Al[(tig + 4) * PSTR + base + 8];
            }
            uint2 wreg[NT8];
#pragma unroll
            for (int nt = 0; nt < NT8; nt++)
                wreg[nt] = Wb[tap * 256 + (nt * 8 + g) * 4 + tig];
#pragma unroll
            for (int nt = 0; nt < NT8; nt++) {       // hi pass
                mma_f16(acc[0][nt], aH[0], wreg[nt].x, wreg[nt].y);
                mma_f16(acc[1][nt], aH[1], wreg[nt].x, wreg[nt].y);
            }
#pragma unroll
            for (int nt = 0; nt < NT8; nt++) {       // lo pass
                mma_f16(acc[0][nt], aL[0], wreg[nt].x, wreg[nt].y);
                mma_f16(acc[1][nt], aL[1], wreg[nt].x, wreg[nt].y);
            }
        }
        __syncthreads();
    }

    // ---- epilogue ----
    const int yout = y0 + wr;
    float* gsm = (float*)smA;              // reused (all reads done)
#pragma unroll
    for (int nt = 0; nt < NT8; nt++) {
        const int co0 = nt * 8 + tig * 2;
        if (COUT < 8 && co0 >= COUT) continue;
        const float bs0 = __ldg(&bias[co0]);
        const float bs1 = __ldg(&bias[co0 + 1]);
#pragma unroll
        for (int mi = 0; mi < 2; mi++) {
            const int px = wx + mi * 16 + g;
            float v0 = acc[mi][nt][0] + bs0;
            float v1 = acc[mi][nt][1] + bs1;
            float v2 = acc[mi][nt][2] + bs0;
            float v3 = acc[mi][nt][3] + bs1;
            if (ACT == 0) {
                v0 = fmaxf(v0, 0.f); v1 = fmaxf(v1, 0.f);
                v2 = fmaxf(v2, 0.f); v3 = fmaxf(v3, 0.f);
            } else if (ACT == 1) {
                v0 = 1.f / (1.f + __expf(-v0)); v1 = 1.f / (1.f + __expf(-v1));
                v2 = 1.f / (1.f + __expf(-v2)); v3 = 1.f / (1.f + __expf(-v3));
            }
            if (TO_F32) {
                float* o0 = outf + ((size_t)b * COUT + co0) * HW
                            + (size_t)yout * W + x0;
                float* o1 = o0 + HW;
                o0[px]     = v0;  o1[px]     = v1;
                o0[px + 8] = v2;  o1[px + 8] = v3;
            } else {
                const int pair = nt * 4 + tig;
                uint32_t h0, l0, h1, l1;
                packA(v0, v1, h0, l0);
                packA(v2, v3, h1, l1);
                size_t o = (size_t)(b * PO + pair) * HW + (size_t)yout * W + x0 + px;
                size_t loO = (size_t)B * PO * HW;
                outs[o]           = h0;
                outs[o + 8]       = h1;
                outs[loO + o]     = l0;
                outs[loO + o + 8] = l1;
            }
            if (FUSE) {                    // gamma -> smem [c][row][px]
                gsm[(co0)     * 264 + wr * 132 + px]     = v0;
                gsm[(co0 + 1) * 264 + wr * 132 + px]     = v1;
                gsm[(co0)     * 264 + wr * 132 + px + 8] = v2;
                gsm[(co0 + 1) * 264 + wr * 132 + px + 8] = v3;
            }
        }
    }

    // ---- fused elementwise stage (conv3 only): fusion_out / sigma / din ----
    if (FUSE) {
        __syncthreads();
        const int row = tid >> 7;          // 0/1
        const int px  = tid & 127;
        const int q   = (y0 + row) * W + x0 + px;
        const float* f0 = ft0 + (size_t)b * 64 * HW + q;
        const float* f1 = ft1 + (size_t)b * 64 * HW + q;
        const float* dv = dd  + (size_t)b * 16 * HW + q;
        float* ofu = out_fusion + (size_t)b * 64 * HW + q;
        float* osg = out_sigma  + (size_t)b * 4 * HW + q;
        const float a = *ca, bo = *cb;
        const size_t loD = (size_t)B * 56 * HW;

        float g4[4];
#pragma unroll
        for (int c = 0; c < 4; c++) g4[c] = gsm[c * 264 + row * 132 + px];

        auto st = [&](int pair, float v0, float v1) {
            uint32_t h, l;
            packA(v0, v1, h, l);
            size_t o = (size_t)(b * 56 + pair) * HW + q;
            din[o] = h;
            din[loD + o] = l;
        };
#pragma unroll
        for (int c = 0; c < 32; c++) {
            float t00 = f0[(size_t)(2 * c) * HW],     t10 = f1[(size_t)(2 * c) * HW];
            float t01 = f0[(size_t)(2 * c + 1) * HW], t11 = f1[(size_t)(2 * c + 1) * HW];
            float gm = g4[c >> 3];
            float r0 = t00 + gm * (t10 - t00);
            float r1 = t01 + gm * (t11 - t01);
            ofu[(size_t)(2 * c) * HW]     = r0;
            ofu[(size_t)(2 * c + 1) * HW] = r1;
            st(c, r0, r1);
        }
#pragma unroll
        for (int j = 0; j < 8; j++)
            st(32 + j, f1[(size_t)(2 * j) * HW], f1[(size_t)(2 * j + 1) * HW]);
#pragma unroll
        for (int j = 0; j < 8; j++)
            st(40 + j, dv[(size_t)(2 * j) * HW], dv[(size_t)(2 * j + 1) * HW]);
        float sg[4];
#pragma unroll
        for (int c = 0; c < 4; c++) {
            float s0 = fminf(fmaxf(f0[(size_t)c * HW], 0.f), 1.f) * a + bo;
            float s1 = fminf(fmaxf(f1[(size_t)c * HW], 0.f), 1.f) * a + bo;
            float om = 1.f - g4[c];
            sg[c] = om * om * s0 + g4[c] * g4[c] * s1;
            osg[(size_t)c * HW] = sg[c];
        }
        st(48, sg[0], sg[1]);
        st(49, sg[2], sg[3]);
    }
}

// ---------------- prep: fusion_in -> pair-packed fp16 hi/lo ------------------
__global__ void prep_kernel(const float* __restrict__ ft0,
                            const float* __restrict__ ft1,
                            const float* __restrict__ gup,
                            const float* __restrict__ ca,
                            const float* __restrict__ cb,
                            uint32_t* __restrict__ fin)
{
    int p = blockIdx.x * blockDim.x + threadIdx.x;
    if (p >= B * HW) return;
    int b = p >> 16;
    int q = p & (HW - 1);
    const float* f0 = ft0 + (size_t)b * 64 * HW + q;
    const float* f1 = ft1 + (size_t)b * 64 * HW + q;
    const float* gu = gup + (size_t)b * 4 * HW + q;
    float a = *ca, bo = *cb;
    const size_t lo_off = (size_t)B * 16 * HW;

    auto st = [&](int pair, float v0, float v1) {
        uint32_t h, l;
        packA(v0, v1, h, l);
        size_t o = (size_t)(b * 16 + pair) * HW + q;
        fin[o] = h;
        fin[lo_off + o] = l;
    };
#pragma unroll
    for (int i = 0; i < 8; i++) {
        float d0 = fabsf(f1[(size_t)(2 * i) * HW]     - f0[(size_t)(2 * i) * HW]);
        float d1 = fabsf(f1[(size_t)(2 * i + 1) * HW] - f0[(size_t)(2 * i + 1) * HW]);
        st(i, d0, d1);
    }
    st(8, gu[0], gu[(size_t)1 * HW]);
    st(9, gu[(size_t)2 * HW], gu[(size_t)3 * HW]);
#pragma unroll
    for (int i = 0; i < 2; i++) {
        float s0 = fminf(fmaxf(f1[(size_t)(2 * i) * HW],     0.f), 1.f) * a + bo;
        float s1 = fminf(fmaxf(f1[(size_t)(2 * i + 1) * HW], 0.f), 1.f) * a + bo;
        st(10 + i, s0, s1);
    }
}

// ---------------- launch -----------------------------------------------------
template <int PA, int PR, int COUT, int NT8, int ACT, int TO_F32, int FUSE>
static inline void launch_conv(const uint32_t* in, const uint2* w,
                               const float* bi, float* of, uint32_t* os,
                               const float* ft0 = nullptr, const float* ft1 = nullptr,
                               const float* dd = nullptr, const float* ca = nullptr,
                               const float* cb = nullptr, float* ofu = nullptr,
                               float* osg = nullptr, uint32_t* din = nullptr)
{
    constexpr int SMEM = (2 * 9088 + 4608) * 4;   // 91136 B -> 2 CTAs/SM
    cudaFuncSetAttribute(conv_f16<PA, PR, COUT, NT8, ACT, TO_F32, FUSE>,
                         cudaFuncAttributeMaxDynamicSharedMemorySize, SMEM);
    conv_f16<PA, PR, COUT, NT8, ACT, TO_F32, FUSE>
        <<<dim3(H, B), 256, SMEM>>>(in, w, bi, of, os,
                                    ft0, ft1, dd, ca, cb, ofu, osg, din);
}

extern "C" void kernel_launch(void* const* d_in, const int* in_sizes, int n_in,
                              void* d_out, int out_size)
{
    const float* ft0 = (const float*)d_in[0];
    const float* ft1 = (const float*)d_in[1];
    const float* gup = (const float*)d_in[2];
    const float* dd  = (const float*)d_in[3];
    const float* ca  = (const float*)d_in[4];
    const float* cb  = (const float*)d_in[5];
    const float* fw1 = (const float*)d_in[6];
    const float* fb1 = (const float*)d_in[7];
    const float* fw2 = (const float*)d_in[8];
    const float* fb2 = (const float*)d_in[9];
    const float* fw3 = (const float*)d_in[10];
    const float* fb3 = (const float*)d_in[11];
    const float* dw1 = (const float*)d_in[12];
    const float* db1 = (const float*)d_in[13];
    const float* dw2 = (const float*)d_in[14];
    const float* db2 = (const float*)d_in[15];
    const float* dw3 = (const float*)d_in[16];
    const float* db3 = (const float*)d_in[17];

    float* out        = (float*)d_out;
    float* out_fusion = out;
    float* out_den    = out + (size_t)B * 64 * HW;
    float* out_gamma  = out + (size_t)2 * B * 64 * HW;
    float* out_sigma  = out_gamma + (size_t)B * 4 * HW;

    float *fin_f, *bufA_f, *bufB_f, *din_f, *wsc_f;
    cudaGetSymbolAddress((void**)&fin_f,  g_fin);
    cudaGetSymbolAddress((void**)&bufA_f, g_bufA);
    cudaGetSymbolAddress((void**)&bufB_f, g_bufB);
    cudaGetSymbolAddress((void**)&din_f,  g_din);
    cudaGetSymbolAddress((void**)&wsc_f,  g_wsc);
    uint32_t* fin  = (uint32_t*)fin_f;
    uint32_t* bufA = (uint32_t*)bufA_f;
    uint32_t* bufB = (uint32_t*)bufB_f;
    uint32_t* din  = (uint32_t*)din_f;
    uint2*    wsc  = (uint2*)wsc_f;

    // chunk offsets (x2304 uint2): w1@0(2) w2@2(4) w3@6(4) w4@10(7) w5@17(4) w6@21(4)
    split_all<<<(25 * 2304 + 255) / 256, 256>>>(fw1, fw2, fw3, dw1, dw2, dw3, wsc);

    prep_kernel<<<(B * HW + 255) / 256, 256>>>(ft0, ft1, gup, ca, cb, fin);

    launch_conv<16, 12, 64, 8, 0, 0, 0>(fin,  wsc,              fb1, nullptr, bufA);
    launch_conv<32, 32, 64, 8, 0, 0, 0>(bufA, wsc + 2  * 2304,  fb2, nullptr, bufB);
    launch_conv<32, 32,  4, 1, 1, 1, 1>(bufB, wsc + 6  * 2304,  fb3, out_gamma, nullptr,
                                        ft0, ft1, dd, ca, cb,
                                        out_fusion, out_sigma, din);
    launch_conv<56, 50, 64, 8, 0, 0, 0>(din,  wsc + 10 * 2304,  db1, nullptr, bufA);
    launch_conv<32, 32, 64, 8, 0, 0, 0>(bufA, wsc + 17 * 2304,  db2, nullptr, bufB);
    launch_conv<32, 32, 64, 8, 2, 1, 0>(bufB, wsc + 21 * 2304,  db3, out_den, nullptr);
}